// round 1
// baseline (speedup 1.0000x reference)
#include <cuda_runtime.h>
#include <cuda_bf16.h>
#include <math.h>

// Problem constants
#define BATCH 4
#define SEQ   2048
#define DMODEL 1024
#define DFFN  2048
#define WIN   64
#define MROWS (BATCH*SEQ)   // 8192
#define EPS   1e-6f

// ---------------- scratch (device globals; no allocation allowed) -------------
__device__ float g_xn  [MROWS * DMODEL];
__device__ float g_q   [MROWS * DMODEL];
__device__ float g_k   [MROWS * DMODEL];
__device__ float g_v   [MROWS * DMODEL];
__device__ float g_att [MROWS * DMODEL];
__device__ float g_xmid[MROWS * DMODEL];
__device__ float g_xn2 [MROWS * DMODEL];
__device__ float g_h1  [MROWS * DFFN];
__device__ float g_h3  [MROWS * DFFN];
__device__ float g_gate[MROWS * DFFN];

// ---------------- RMSNorm: one block per row, D=1024, 256 threads -------------
__global__ void rmsnorm_kernel(const float* __restrict__ x,
                               const float* __restrict__ w,
                               float* __restrict__ out) {
    const int D = DMODEL;
    size_t row = blockIdx.x;
    const float4* xr = reinterpret_cast<const float4*>(x + row * D);
    const float4* wr = reinterpret_cast<const float4*>(w);
    float4* orow = reinterpret_cast<float4*>(out + row * D);

    int tid = threadIdx.x;           // 256 threads, 4 floats each
    float4 xv = xr[tid];
    float ss = xv.x*xv.x + xv.y*xv.y + xv.z*xv.z + xv.w*xv.w;

    // warp reduce
    #pragma unroll
    for (int off = 16; off; off >>= 1)
        ss += __shfl_xor_sync(0xffffffffu, ss, off);

    __shared__ float red[8];
    int lane = tid & 31, warp = tid >> 5;
    if (lane == 0) red[warp] = ss;
    __syncthreads();
    if (tid < 32) {
        float v = (tid < 8) ? red[tid] : 0.0f;
        #pragma unroll
        for (int off = 4; off; off >>= 1)
            v += __shfl_xor_sync(0xffffffffu, v, off);
        if (tid == 0) red[0] = rsqrtf(v * (1.0f / D) + EPS);
    }
    __syncthreads();
    float inv = red[0];

    float4 wv = wr[tid];
    float4 o;
    o.x = xv.x * inv * wv.x;
    o.y = xv.y * inv * wv.y;
    o.z = xv.z * inv * wv.z;
    o.w = xv.w * inv * wv.w;
    orow[tid] = o;
}

// ---------------- SGEMM: C[M,N] = A[M,K] @ B[K,N] (+ R) -----------------------
// 128x128 tile, BK=16, 256 threads, 8x8 per thread. M%128==0, N%128==0, K%16==0.
#define BM 128
#define BN 128
#define BK 16
#define TM 8
#define TN 8

__global__ __launch_bounds__(256, 2)
void sgemm_kernel(const float* __restrict__ A, const float* __restrict__ B,
                  const float* __restrict__ R, float* __restrict__ C,
                  int M, int N, int K) {
    __shared__ float As[BK][BM + 4];   // stored transposed: As[k][m]
    __shared__ float Bs[BK][BN + 4];

    const int bx = blockIdx.x;   // N tile
    const int by = blockIdx.y;   // M tile
    const int tid = threadIdx.x;
    const int tx = tid & 15;     // 0..15 (N direction)
    const int ty = tid >> 4;     // 0..15 (M direction)

    const float* Ab = A + (size_t)by * BM * K;
    const float* Bb = B + (size_t)bx * BN;

    // A-tile load map: 128 rows x 16 cols; each thread: 2 float4
    const int arow = tid >> 2;          // 0..63
    const int acol = (tid & 3) * 4;     // 0,4,8,12
    // B-tile load map: 16 rows x 128 cols; each thread: 2 float4
    const int brow = tid >> 5;          // 0..7
    const int bcol = (tid & 31) * 4;    // 0..124

    float acc[TM][TN];
    #pragma unroll
    for (int i = 0; i < TM; i++)
        #pragma unroll
        for (int j = 0; j < TN; j++) acc[i][j] = 0.0f;

    for (int k0 = 0; k0 < K; k0 += BK) {
        float4 a0 = *reinterpret_cast<const float4*>(Ab + (size_t)arow        * K + k0 + acol);
        float4 a1 = *reinterpret_cast<const float4*>(Ab + (size_t)(arow + 64) * K + k0 + acol);
        float4 b0 = *reinterpret_cast<const float4*>(Bb + (size_t)(k0 + brow    ) * N + bcol);
        float4 b1 = *reinterpret_cast<const float4*>(Bb + (size_t)(k0 + brow + 8) * N + bcol);

        As[acol + 0][arow] = a0.x;  As[acol + 1][arow] = a0.y;
        As[acol + 2][arow] = a0.z;  As[acol + 3][arow] = a0.w;
        As[acol + 0][arow + 64] = a1.x;  As[acol + 1][arow + 64] = a1.y;
        As[acol + 2][arow + 64] = a1.z;  As[acol + 3][arow + 64] = a1.w;
        *reinterpret_cast<float4*>(&Bs[brow    ][bcol]) = b0;
        *reinterpret_cast<float4*>(&Bs[brow + 8][bcol]) = b1;
        __syncthreads();

        #pragma unroll
        for (int kk = 0; kk < BK; kk++) {
            float4 ar0 = *reinterpret_cast<const float4*>(&As[kk][ty * TM]);
            float4 ar1 = *reinterpret_cast<const float4*>(&As[kk][ty * TM + 4]);
            float4 br0 = *reinterpret_cast<const float4*>(&Bs[kk][tx * TN]);
            float4 br1 = *reinterpret_cast<const float4*>(&Bs[kk][tx * TN + 4]);
            float ar[TM] = {ar0.x, ar0.y, ar0.z, ar0.w, ar1.x, ar1.y, ar1.z, ar1.w};
            float br[TN] = {br0.x, br0.y, br0.z, br0.w, br1.x, br1.y, br1.z, br1.w};
            #pragma unroll
            for (int i = 0; i < TM; i++)
                #pragma unroll
                for (int j = 0; j < TN; j++)
                    acc[i][j] = fmaf(ar[i], br[j], acc[i][j]);
        }
        __syncthreads();
    }

    // epilogue: optional residual add, float4 stores
    const int crow0 = by * BM + ty * TM;
    const int ccol0 = bx * BN + tx * TN;
    #pragma unroll
    for (int i = 0; i < TM; i++) {
        size_t off = (size_t)(crow0 + i) * N + ccol0;
        float4 o0 = make_float4(acc[i][0], acc[i][1], acc[i][2], acc[i][3]);
        float4 o1 = make_float4(acc[i][4], acc[i][5], acc[i][6], acc[i][7]);
        if (R) {
            float4 r0 = *reinterpret_cast<const float4*>(R + off);
            float4 r1 = *reinterpret_cast<const float4*>(R + off + 4);
            o0.x += r0.x; o0.y += r0.y; o0.z += r0.z; o0.w += r0.w;
            o1.x += r1.x; o1.y += r1.y; o1.z += r1.z; o1.w += r1.w;
        }
        *reinterpret_cast<float4*>(C + off)     = o0;
        *reinterpret_cast<float4*>(C + off + 4) = o1;
    }
}

// ---------------- Windowed causal attention ----------------------------------
// One block per (b, i) query. 256 threads (8 warps).
__global__ void attn_kernel(const float* __restrict__ q,
                            const float* __restrict__ k,
                            const float* __restrict__ v,
                            float* __restrict__ out) {
    const int D = DMODEL, T = SEQ, W = WIN;
    const float scale = 0.03125f;  // 1/sqrt(1024)

    int b = blockIdx.x / T;
    int i = blockIdx.x % T;
    size_t qoff = ((size_t)b * T + i) * D;

    __shared__ float qs[DMODEL];
    __shared__ float sc[WIN];

    int tid = threadIdx.x;
    int warp = tid >> 5, lane = tid & 31;

    #pragma unroll
    for (int r = 0; r < 4; r++) qs[tid + r * 256] = q[qoff + tid + r * 256];
    __syncthreads();

    int j0 = (i >= W - 1) ? (i - W + 1) : 0;
    int nj = i - j0 + 1;

    // scores: each warp takes j strided by 8
    for (int jj = warp; jj < nj; jj += 8) {
        const float* krow = k + ((size_t)b * T + j0 + jj) * D;
        float s = 0.0f;
        #pragma unroll 8
        for (int d = lane; d < D; d += 32) s = fmaf(qs[d], krow[d], s);
        #pragma unroll
        for (int off = 16; off; off >>= 1)
            s += __shfl_xor_sync(0xffffffffu, s, off);
        if (lane == 0) sc[jj] = s * scale;
    }
    __syncthreads();

    // softmax over nj (<=64) scores, done by warp 0
    if (tid < 32) {
        float s0 = (tid < nj)      ? sc[tid]      : -1e30f;
        float s1 = (tid + 32 < nj) ? sc[tid + 32] : -1e30f;
        float m = fmaxf(s0, s1);
        #pragma unroll
        for (int off = 16; off; off >>= 1)
            m = fmaxf(m, __shfl_xor_sync(0xffffffffu, m, off));
        float e0 = __expf(s0 - m);
        float e1 = __expf(s1 - m);
        if (tid >= nj)      e0 = 0.0f;
        if (tid + 32 >= nj) e1 = 0.0f;
        float sum = e0 + e1;
        #pragma unroll
        for (int off = 16; off; off >>= 1)
            sum += __shfl_xor_sync(0xffffffffu, sum, off);
        float inv = 1.0f / sum;
        if (tid < nj)      sc[tid]      = e0 * inv;
        if (tid + 32 < nj) sc[tid + 32] = e1 * inv;
    }
    __syncthreads();

    // attended = sum_j w_j * v_j ; threads own 4 d-slots each (coalesced)
    float acc0 = 0.f, acc1 = 0.f, acc2 = 0.f, acc3 = 0.f;
    for (int jj = 0; jj < nj; jj++) {
        float wgt = sc[jj];
        const float* vrow = v + ((size_t)b * T + j0 + jj) * D;
        acc0 = fmaf(wgt, vrow[tid          ], acc0);
        acc1 = fmaf(wgt, vrow[tid +  256   ], acc1);
        acc2 = fmaf(wgt, vrow[tid +  512   ], acc2);
        acc3 = fmaf(wgt, vrow[tid +  768   ], acc3);
    }
    out[qoff + tid       ] = acc0;
    out[qoff + tid +  256] = acc1;
    out[qoff + tid +  512] = acc2;
    out[qoff + tid +  768] = acc3;
}

// ---------------- SwiGLU elementwise ------------------------------------------
__global__ void swiglu_kernel(const float* __restrict__ h1,
                              const float* __restrict__ h3,
                              float* __restrict__ g, int n4) {
    int idx = blockIdx.x * blockDim.x + threadIdx.x;
    if (idx >= n4) return;
    float4 a = reinterpret_cast<const float4*>(h1)[idx];
    float4 c = reinterpret_cast<const float4*>(h3)[idx];
    float4 o;
    o.x = a.x / (1.0f + __expf(-a.x)) * c.x;
    o.y = a.y / (1.0f + __expf(-a.y)) * c.y;
    o.z = a.z / (1.0f + __expf(-a.z)) * c.z;
    o.w = a.w / (1.0f + __expf(-a.w)) * c.w;
    reinterpret_cast<float4*>(g)[idx] = o;
}

// ---------------- launch -------------------------------------------------------
extern "C" void kernel_launch(void* const* d_in, const int* in_sizes, int n_in,
                              void* d_out, int out_size) {
    const float* x       = (const float*)d_in[0];
    const float* norm1_w = (const float*)d_in[1];
    const float* norm2_w = (const float*)d_in[2];
    const float* Wq      = (const float*)d_in[3];
    const float* Wk      = (const float*)d_in[4];
    const float* Wv      = (const float*)d_in[5];
    const float* Wo      = (const float*)d_in[6];
    const float* W1      = (const float*)d_in[7];
    const float* W2      = (const float*)d_in[8];
    const float* W3      = (const float*)d_in[9];
    float* out = (float*)d_out;

    float *p_xn, *p_q, *p_k, *p_v, *p_att, *p_xmid, *p_xn2, *p_h1, *p_h3, *p_gate;
    cudaGetSymbolAddress((void**)&p_xn,   g_xn);
    cudaGetSymbolAddress((void**)&p_q,    g_q);
    cudaGetSymbolAddress((void**)&p_k,    g_k);
    cudaGetSymbolAddress((void**)&p_v,    g_v);
    cudaGetSymbolAddress((void**)&p_att,  g_att);
    cudaGetSymbolAddress((void**)&p_xmid, g_xmid);
    cudaGetSymbolAddress((void**)&p_xn2,  g_xn2);
    cudaGetSymbolAddress((void**)&p_h1,   g_h1);
    cudaGetSymbolAddress((void**)&p_h3,   g_h3);
    cudaGetSymbolAddress((void**)&p_gate, g_gate);

    const int M = MROWS;           // 8192
    dim3 gD(DMODEL / BN, M / BM);  // (8, 64)
    dim3 gF(DFFN   / BN, M / BM);  // (16, 64)

    // 1. norm1
    rmsnorm_kernel<<<M, 256>>>(x, norm1_w, p_xn);
    // 2. Q, K, V projections
    sgemm_kernel<<<gD, 256>>>(p_xn, Wq, nullptr, p_q, M, DMODEL, DMODEL);
    sgemm_kernel<<<gD, 256>>>(p_xn, Wk, nullptr, p_k, M, DMODEL, DMODEL);
    sgemm_kernel<<<gD, 256>>>(p_xn, Wv, nullptr, p_v, M, DMODEL, DMODEL);
    // 3. windowed attention
    attn_kernel<<<M, 256>>>(p_q, p_k, p_v, p_att);
    // 4. x_mid = x + attended @ Wo
    sgemm_kernel<<<gD, 256>>>(p_att, Wo, x, p_xmid, M, DMODEL, DMODEL);
    // 5. norm2
    rmsnorm_kernel<<<M, 256>>>(p_xmid, norm2_w, p_xn2);
    // 6. FFN up projections
    sgemm_kernel<<<gF, 256>>>(p_xn2, W1, nullptr, p_h1, M, DFFN, DMODEL);
    sgemm_kernel<<<gF, 256>>>(p_xn2, W3, nullptr, p_h3, M, DFFN, DMODEL);
    // 7. gate = silu(h1) * h3
    {
        int n4 = M * DFFN / 4;
        swiglu_kernel<<<(n4 + 255) / 256, 256>>>(p_h1, p_h3, p_gate, n4);
    }
    // 8. out = x_mid + gate @ W2
    sgemm_kernel<<<gD, 256>>>(p_gate, W2, p_xmid, out, M, DMODEL, DFFN);
}

// round 3
// speedup vs baseline: 1.8073x; 1.8073x over previous
#include <cuda_runtime.h>
#include <cuda_bf16.h>
#include <cstdint>
#include <math.h>

// Problem constants
#define BATCH 4
#define SEQ   2048
#define DMODEL 1024
#define DFFN  2048
#define WIN   64
#define MROWS (BATCH*SEQ)   // 8192
#define EPS   1e-6f

// ---------------- scratch (device globals; no allocation allowed) -------------
__device__ float g_q   [MROWS * DMODEL];
__device__ float g_k   [MROWS * DMODEL];
__device__ float g_v   [MROWS * DMODEL];
__device__ float g_xmid[MROWS * DMODEL];
__device__ float g_h1  [MROWS * DFFN];
__device__ float g_h3  [MROWS * DFFN];
// bf16 split activations (A operands, [M,K])
__device__ __nv_bfloat16 g_xn_h [MROWS * DMODEL];
__device__ __nv_bfloat16 g_xn_l [MROWS * DMODEL];
__device__ __nv_bfloat16 g_att_h[MROWS * DMODEL];
__device__ __nv_bfloat16 g_att_l[MROWS * DMODEL];
__device__ __nv_bfloat16 g_xn2_h[MROWS * DMODEL];
__device__ __nv_bfloat16 g_xn2_l[MROWS * DMODEL];
__device__ __nv_bfloat16 g_gate_h[MROWS * DFFN];
__device__ __nv_bfloat16 g_gate_l[MROWS * DFFN];
// bf16 split + transposed weights [N,K]
__device__ __nv_bfloat16 g_wq_h[DMODEL * DMODEL];
__device__ __nv_bfloat16 g_wq_l[DMODEL * DMODEL];
__device__ __nv_bfloat16 g_wk_h[DMODEL * DMODEL];
__device__ __nv_bfloat16 g_wk_l[DMODEL * DMODEL];
__device__ __nv_bfloat16 g_wv_h[DMODEL * DMODEL];
__device__ __nv_bfloat16 g_wv_l[DMODEL * DMODEL];
__device__ __nv_bfloat16 g_wo_h[DMODEL * DMODEL];
__device__ __nv_bfloat16 g_wo_l[DMODEL * DMODEL];
__device__ __nv_bfloat16 g_w1_h[DFFN * DMODEL];
__device__ __nv_bfloat16 g_w1_l[DFFN * DMODEL];
__device__ __nv_bfloat16 g_w3_h[DFFN * DMODEL];
__device__ __nv_bfloat16 g_w3_l[DFFN * DMODEL];
__device__ __nv_bfloat16 g_w2_h[DMODEL * DFFN];
__device__ __nv_bfloat16 g_w2_l[DMODEL * DFFN];

// ============================= PTX helpers ====================================
__device__ __forceinline__ uint32_t smem_u32(const void* p) {
    uint32_t a;
    asm("{ .reg .u64 t; cvta.to.shared.u64 t, %1; cvt.u32.u64 %0, t; }"
        : "=r"(a) : "l"(p));
    return a;
}
__device__ __forceinline__ uint32_t swz128(uint32_t o) {
    return o ^ ((o >> 3) & 0x70);
}
__device__ __forceinline__ void cpasync16(uint32_t dst, const void* src) {
    asm volatile("cp.async.cg.shared.global [%0], [%1], 16;"
                 :: "r"(dst), "l"(__cvta_generic_to_global(src)) : "memory");
}
__device__ __forceinline__ void cp_commit() {
    asm volatile("cp.async.commit_group;" ::: "memory");
}
template <int N>
__device__ __forceinline__ void cp_wait() {
    asm volatile("cp.async.wait_group %0;" :: "n"(N) : "memory");
}
__device__ __forceinline__ void ldsm_x4(uint32_t* r, uint32_t addr) {
    asm volatile("ldmatrix.sync.aligned.m8n8.x4.shared.b16 {%0,%1,%2,%3}, [%4];"
                 : "=r"(r[0]), "=r"(r[1]), "=r"(r[2]), "=r"(r[3]) : "r"(addr));
}
__device__ __forceinline__ void mma16816(float* c, const uint32_t* a,
                                         uint32_t b0, uint32_t b1) {
    asm volatile(
        "mma.sync.aligned.m16n8k16.row.col.f32.bf16.bf16.f32 "
        "{%0,%1,%2,%3}, {%4,%5,%6,%7}, {%8,%9}, {%0,%1,%2,%3};"
        : "+f"(c[0]), "+f"(c[1]), "+f"(c[2]), "+f"(c[3])
        : "r"(a[0]), "r"(a[1]), "r"(a[2]), "r"(a[3]), "r"(b0), "r"(b1));
}

// ====================== bf16x3 GEMM via mma.sync ==============================
// C[M,N] = (Ah+Al)[M,K] @ (Bh+Bl)[N,K]^T (+R), fp32 out.
// Tile 128x128, BK=64, 256 threads (8 warps, 4x2), 3-stage cp.async pipeline.
#define GBM 128
#define GBN 128
#define GBK 64
#define NSTAGE 3
#define AH_OFF 0
#define AL_OFF 16384
#define BH_OFF 32768
#define BL_OFF 49152
#define STAGE_BYTES 65536
#define GEMM_SMEM (NSTAGE * STAGE_BYTES)

__device__ __forceinline__ void gemm_load_stage(
    uint32_t sb,
    const __nv_bfloat16* __restrict__ Ah, const __nv_bfloat16* __restrict__ Al,
    const __nv_bfloat16* __restrict__ Bh, const __nv_bfloat16* __restrict__ Bl,
    int m0, int n0, int k0, int K, int tid)
{
    const int row  = tid >> 1;            // 0..127
    const int half = (tid & 1) * 64;      // byte offset within 128B row
    const uint32_t so = row * 128 + half;

    const char* pAh = (const char*)(Ah + (size_t)(m0 + row) * K + k0) + half;
    const char* pAl = (const char*)(Al + (size_t)(m0 + row) * K + k0) + half;
    const char* pBh = (const char*)(Bh + (size_t)(n0 + row) * K + k0) + half;
    const char* pBl = (const char*)(Bl + (size_t)(n0 + row) * K + k0) + half;

    #pragma unroll
    for (int s = 0; s < 4; ++s) {
        uint32_t d = swz128(so + s * 16);
        cpasync16(sb + AH_OFF + d, pAh + s * 16);
        cpasync16(sb + AL_OFF + d, pAl + s * 16);
        cpasync16(sb + BH_OFF + d, pBh + s * 16);
        cpasync16(sb + BL_OFF + d, pBl + s * 16);
    }
}

__global__ __launch_bounds__(256, 1)
void gemm_bf16x3(const __nv_bfloat16* __restrict__ Ah, const __nv_bfloat16* __restrict__ Al,
                 const __nv_bfloat16* __restrict__ Bh, const __nv_bfloat16* __restrict__ Bl,
                 const float* __restrict__ R, float* __restrict__ C,
                 int N, int K)
{
    extern __shared__ char smem[];
    const int tid  = threadIdx.x;
    const int wid  = tid >> 5;
    const int lane = tid & 31;
    const int m0 = blockIdx.y * GBM;
    const int n0 = blockIdx.x * GBN;
    const int nk = K / GBK;

    const uint32_t base = smem_u32(smem);
    const int wm0 = (wid & 3) * 32;   // warp row offset in tile
    const int wn0 = (wid >> 2) * 64;  // warp col offset in tile

    float acc[2][8][4];
    #pragma unroll
    for (int i = 0; i < 2; ++i)
        #pragma unroll
        for (int j = 0; j < 8; ++j)
            #pragma unroll
            for (int t = 0; t < 4; ++t) acc[i][j][t] = 0.0f;

    // prologue: stages 0..NSTAGE-2
    #pragma unroll
    for (int p = 0; p < NSTAGE - 1; ++p) {
        gemm_load_stage(base + p * STAGE_BYTES, Ah, Al, Bh, Bl, m0, n0, p * GBK, K, tid);
        cp_commit();
    }

    // precomputed lane addressing pieces
    const uint32_t lrow  = (lane & 15);
    const uint32_t lkoff = (lane >> 4) << 4;

    for (int i = 0; i < nk; ++i) {
        cp_wait<NSTAGE - 2>();
        __syncthreads();

        const uint32_t sb = base + (i % NSTAGE) * STAGE_BYTES;
        #pragma unroll
        for (int ks = 0; ks < 4; ++ks) {
            uint32_t ah[2][4], al[2][4], bh[4][4], bl[4][4];
            #pragma unroll
            for (int ma = 0; ma < 2; ++ma) {
                uint32_t off = (wm0 + ma * 16 + lrow) * 128 + ks * 32 + lkoff;
                uint32_t ad = sb + swz128(off);
                ldsm_x4(ah[ma], ad + AH_OFF);
                ldsm_x4(al[ma], ad + AL_OFF);
            }
            #pragma unroll
            for (int ng = 0; ng < 4; ++ng) {
                uint32_t off = (wn0 + ng * 16 + lrow) * 128 + ks * 32 + lkoff;
                uint32_t bd = sb + swz128(off);
                ldsm_x4(bh[ng], bd + BH_OFF);
                ldsm_x4(bl[ng], bd + BL_OFF);
            }
            #pragma unroll
            for (int ma = 0; ma < 2; ++ma)
                #pragma unroll
                for (int ng = 0; ng < 4; ++ng)
                    #pragma unroll
                    for (int h = 0; h < 2; ++h) {
                        const int na = ng * 2 + h;
                        mma16816(acc[ma][na], ah[ma], bh[ng][h], bh[ng][2 + h]);
                        mma16816(acc[ma][na], ah[ma], bl[ng][h], bl[ng][2 + h]);
                        mma16816(acc[ma][na], al[ma], bh[ng][h], bh[ng][2 + h]);
                    }
        }
        __syncthreads();

        const int nc = i + NSTAGE - 1;
        if (nc < nk)
            gemm_load_stage(base + (nc % NSTAGE) * STAGE_BYTES,
                            Ah, Al, Bh, Bl, m0, n0, nc * GBK, K, tid);
        cp_commit();   // uniform commit keeps wait_group arithmetic exact
    }

    // epilogue: direct stores (float2), optional residual
    const int mrow = lane >> 2;          // 0..7
    const int ncol = (lane & 3) * 2;
    #pragma unroll
    for (int ma = 0; ma < 2; ++ma) {
        #pragma unroll
        for (int na = 0; na < 8; ++na) {
            const int m = m0 + wm0 + ma * 16 + mrow;
            const int n = n0 + wn0 + na * 8 + ncol;
            size_t o0 = (size_t)m * N + n;
            size_t o1 = o0 + (size_t)8 * N;
            float2 v0 = make_float2(acc[ma][na][0], acc[ma][na][1]);
            float2 v1 = make_float2(acc[ma][na][2], acc[ma][na][3]);
            if (R) {
                float2 r0 = *reinterpret_cast<const float2*>(R + o0);
                float2 r1 = *reinterpret_cast<const float2*>(R + o1);
                v0.x += r0.x; v0.y += r0.y;
                v1.x += r1.x; v1.y += r1.y;
            }
            *reinterpret_cast<float2*>(C + o0) = v0;
            *reinterpret_cast<float2*>(C + o1) = v1;
        }
    }
}

// ================= weight transpose + bf16 split: [K,N]f32 -> [N,K]bf16 x2 ====
__global__ void wsplit_kernel(const float* __restrict__ W,
                              __nv_bfloat16* __restrict__ Th,
                              __nv_bfloat16* __restrict__ Tl,
                              int K, int N)
{
    __shared__ float t[32][33];
    int n0 = blockIdx.x * 32, k0 = blockIdx.y * 32;
    int tx = threadIdx.x & 31, ty = threadIdx.x >> 5;   // 256 thr: ty 0..7
    #pragma unroll
    for (int r = ty; r < 32; r += 8)
        t[r][tx] = W[(size_t)(k0 + r) * N + n0 + tx];
    __syncthreads();
    #pragma unroll
    for (int r = ty; r < 32; r += 8) {
        float v = t[tx][r];                       // W[k0+tx][n0+r]
        __nv_bfloat16 h = __float2bfloat16(v);
        __nv_bfloat16 l = __float2bfloat16(v - __bfloat162float(h));
        size_t o = (size_t)(n0 + r) * K + k0 + tx;
        Th[o] = h; Tl[o] = l;
    }
}

// ---------------- RMSNorm + bf16 split ----------------------------------------
__global__ void rmsnorm_split_kernel(const float* __restrict__ x,
                                     const float* __restrict__ w,
                                     __nv_bfloat16* __restrict__ oh,
                                     __nv_bfloat16* __restrict__ ol) {
    const int D = DMODEL;
    size_t row = blockIdx.x;
    const float4* xr = reinterpret_cast<const float4*>(x + row * D);
    const float4* wr = reinterpret_cast<const float4*>(w);

    int tid = threadIdx.x;
    float4 xv = xr[tid];
    float ss = xv.x*xv.x + xv.y*xv.y + xv.z*xv.z + xv.w*xv.w;
    #pragma unroll
    for (int off = 16; off; off >>= 1)
        ss += __shfl_xor_sync(0xffffffffu, ss, off);
    __shared__ float red[8];
    int lane = tid & 31, warp = tid >> 5;
    if (lane == 0) red[warp] = ss;
    __syncthreads();
    if (tid < 32) {
        float v = (tid < 8) ? red[tid] : 0.0f;
        #pragma unroll
        for (int off = 4; off; off >>= 1)
            v += __shfl_xor_sync(0xffffffffu, v, off);
        if (tid == 0) red[0] = rsqrtf(v * (1.0f / D) + EPS);
    }
    __syncthreads();
    float inv = red[0];
    float4 wv = wr[tid];
    float f[4];
    f[0] = xv.x * inv * wv.x; f[1] = xv.y * inv * wv.y;
    f[2] = xv.z * inv * wv.z; f[3] = xv.w * inv * wv.w;

    alignas(8) __nv_bfloat16 hv[4], lv[4];
    #pragma unroll
    for (int j = 0; j < 4; ++j) {
        hv[j] = __float2bfloat16(f[j]);
        lv[j] = __float2bfloat16(f[j] - __bfloat162float(hv[j]));
    }
    size_t b = row * D + tid * 4;
    *reinterpret_cast<uint2*>(oh + b) = *reinterpret_cast<uint2*>(hv);
    *reinterpret_cast<uint2*>(ol + b) = *reinterpret_cast<uint2*>(lv);
}

// ---------------- Windowed causal attention (fp32 in, bf16-split out) ---------
__global__ void attn_kernel(const float* __restrict__ q,
                            const float* __restrict__ k,
                            const float* __restrict__ v,
                            __nv_bfloat16* __restrict__ oh,
                            __nv_bfloat16* __restrict__ ol) {
    const int D = DMODEL, T = SEQ, W = WIN;
    const float scale = 0.03125f;  // 1/sqrt(1024)

    int b = blockIdx.x / T;
    int i = blockIdx.x % T;
    size_t qoff = ((size_t)b * T + i) * D;

    __shared__ float qs[DMODEL];
    __shared__ float sc[WIN];

    int tid = threadIdx.x;
    int warp = tid >> 5, lane = tid & 31;

    #pragma unroll
    for (int r = 0; r < 4; r++) qs[tid + r * 256] = q[qoff + tid + r * 256];
    __syncthreads();

    int j0 = (i >= W - 1) ? (i - W + 1) : 0;
    int nj = i - j0 + 1;

    for (int jj = warp; jj < nj; jj += 8) {
        const float* krow = k + ((size_t)b * T + j0 + jj) * D;
        float s = 0.0f;
        #pragma unroll 8
        for (int d = lane; d < D; d += 32) s = fmaf(qs[d], krow[d], s);
        #pragma unroll
        for (int off = 16; off; off >>= 1)
            s += __shfl_xor_sync(0xffffffffu, s, off);
        if (lane == 0) sc[jj] = s * scale;
    }
    __syncthreads();

    if (tid < 32) {
        float s0 = (tid < nj)      ? sc[tid]      : -1e30f;
        float s1 = (tid + 32 < nj) ? sc[tid + 32] : -1e30f;
        float m = fmaxf(s0, s1);
        #pragma unroll
        for (int off = 16; off; off >>= 1)
            m = fmaxf(m, __shfl_xor_sync(0xffffffffu, m, off));
        float e0 = __expf(s0 - m);
        float e1 = __expf(s1 - m);
        if (tid >= nj)      e0 = 0.0f;
        if (tid + 32 >= nj) e1 = 0.0f;
        float sum = e0 + e1;
        #pragma unroll
        for (int off = 16; off; off >>= 1)
            sum += __shfl_xor_sync(0xffffffffu, sum, off);
        float inv = 1.0f / sum;
        if (tid < nj)      sc[tid]      = e0 * inv;
        if (tid + 32 < nj) sc[tid + 32] = e1 * inv;
    }
    __syncthreads();

    float acc[4] = {0.f, 0.f, 0.f, 0.f};
    for (int jj = 0; jj < nj; jj++) {
        float wgt = sc[jj];
        const float* vrow = v + ((size_t)b * T + j0 + jj) * D;
        acc[0] = fmaf(wgt, vrow[tid      ], acc[0]);
        acc[1] = fmaf(wgt, vrow[tid + 256], acc[1]);
        acc[2] = fmaf(wgt, vrow[tid + 512], acc[2]);
        acc[3] = fmaf(wgt, vrow[tid + 768], acc[3]);
    }
    #pragma unroll
    for (int r = 0; r < 4; ++r) {
        __nv_bfloat16 h = __float2bfloat16(acc[r]);
        __nv_bfloat16 l = __float2bfloat16(acc[r] - __bfloat162float(h));
        oh[qoff + tid + r * 256] = h;
        ol[qoff + tid + r * 256] = l;
    }
}

// ---------------- SwiGLU + bf16 split -----------------------------------------
__global__ void swiglu_split_kernel(const float* __restrict__ h1,
                                    const float* __restrict__ h3,
                                    __nv_bfloat16* __restrict__ gh,
                                    __nv_bfloat16* __restrict__ gl, int n4) {
    int idx = blockIdx.x * blockDim.x + threadIdx.x;
    if (idx >= n4) return;
    float4 a = reinterpret_cast<const float4*>(h1)[idx];
    float4 c = reinterpret_cast<const float4*>(h3)[idx];
    float f[4];
    f[0] = a.x / (1.0f + __expf(-a.x)) * c.x;
    f[1] = a.y / (1.0f + __expf(-a.y)) * c.y;
    f[2] = a.z / (1.0f + __expf(-a.z)) * c.z;
    f[3] = a.w / (1.0f + __expf(-a.w)) * c.w;
    alignas(8) __nv_bfloat16 hv[4], lv[4];
    #pragma unroll
    for (int j = 0; j < 4; ++j) {
        hv[j] = __float2bfloat16(f[j]);
        lv[j] = __float2bfloat16(f[j] - __bfloat162float(hv[j]));
    }
    *reinterpret_cast<uint2*>(gh + (size_t)idx * 4) = *reinterpret_cast<uint2*>(hv);
    *reinterpret_cast<uint2*>(gl + (size_t)idx * 4) = *reinterpret_cast<uint2*>(lv);
}

// ---------------- launch -------------------------------------------------------
extern "C" void kernel_launch(void* const* d_in, const int* in_sizes, int n_in,
                              void* d_out, int out_size) {
    const float* x       = (const float*)d_in[0];
    const float* norm1_w = (const float*)d_in[1];
    const float* norm2_w = (const float*)d_in[2];
    const float* Wq      = (const float*)d_in[3];
    const float* Wk      = (const float*)d_in[4];
    const float* Wv      = (const float*)d_in[5];
    const float* Wo      = (const float*)d_in[6];
    const float* W1      = (const float*)d_in[7];
    const float* W2      = (const float*)d_in[8];
    const float* W3      = (const float*)d_in[9];
    float* out = (float*)d_out;

    float *p_q, *p_k, *p_v, *p_xmid, *p_h1, *p_h3;
    cudaGetSymbolAddress((void**)&p_q,    g_q);
    cudaGetSymbolAddress((void**)&p_k,    g_k);
    cudaGetSymbolAddress((void**)&p_v,    g_v);
    cudaGetSymbolAddress((void**)&p_xmid, g_xmid);
    cudaGetSymbolAddress((void**)&p_h1,   g_h1);
    cudaGetSymbolAddress((void**)&p_h3,   g_h3);

    __nv_bfloat16 *xn_h, *xn_l, *att_h, *att_l, *xn2_h, *xn2_l, *gate_h, *gate_l;
    cudaGetSymbolAddress((void**)&xn_h,  g_xn_h);
    cudaGetSymbolAddress((void**)&xn_l,  g_xn_l);
    cudaGetSymbolAddress((void**)&att_h, g_att_h);
    cudaGetSymbolAddress((void**)&att_l, g_att_l);
    cudaGetSymbolAddress((void**)&xn2_h, g_xn2_h);
    cudaGetSymbolAddress((void**)&xn2_l, g_xn2_l);
    cudaGetSymbolAddress((void**)&gate_h, g_gate_h);
    cudaGetSymbolAddress((void**)&gate_l, g_gate_l);

    __nv_bfloat16 *wq_h, *wq_l, *wk_h, *wk_l, *wv_h, *wv_l, *wo_h, *wo_l;
    __nv_bfloat16 *w1_h, *w1_l, *w3_h, *w3_l, *w2_h, *w2_l;
    cudaGetSymbolAddress((void**)&wq_h, g_wq_h);  cudaGetSymbolAddress((void**)&wq_l, g_wq_l);
    cudaGetSymbolAddress((void**)&wk_h, g_wk_h);  cudaGetSymbolAddress((void**)&wk_l, g_wk_l);
    cudaGetSymbolAddress((void**)&wv_h, g_wv_h);  cudaGetSymbolAddress((void**)&wv_l, g_wv_l);
    cudaGetSymbolAddress((void**)&wo_h, g_wo_h);  cudaGetSymbolAddress((void**)&wo_l, g_wo_l);
    cudaGetSymbolAddress((void**)&w1_h, g_w1_h);  cudaGetSymbolAddress((void**)&w1_l, g_w1_l);
    cudaGetSymbolAddress((void**)&w3_h, g_w3_h);  cudaGetSymbolAddress((void**)&w3_l, g_w3_l);
    cudaGetSymbolAddress((void**)&w2_h, g_w2_h);  cudaGetSymbolAddress((void**)&w2_l, g_w2_l);

    cudaFuncSetAttribute(gemm_bf16x3, cudaFuncAttributeMaxDynamicSharedMemorySize, GEMM_SMEM);

    const int M = MROWS;              // 8192
    dim3 gD(DMODEL / GBN, M / GBM);   // (8, 64)
    dim3 gF(DFFN   / GBN, M / GBM);   // (16, 64)

    // weight transpose + split
    wsplit_kernel<<<dim3(DMODEL/32, DMODEL/32), 256>>>(Wq, wq_h, wq_l, DMODEL, DMODEL);
    wsplit_kernel<<<dim3(DMODEL/32, DMODEL/32), 256>>>(Wk, wk_h, wk_l, DMODEL, DMODEL);
    wsplit_kernel<<<dim3(DMODEL/32, DMODEL/32), 256>>>(Wv, wv_h, wv_l, DMODEL, DMODEL);
    wsplit_kernel<<<dim3(DMODEL/32, DMODEL/32), 256>>>(Wo, wo_h, wo_l, DMODEL, DMODEL);
    wsplit_kernel<<<dim3(DFFN/32,   DMODEL/32), 256>>>(W1, w1_h, w1_l, DMODEL, DFFN);
    wsplit_kernel<<<dim3(DFFN/32,   DMODEL/32), 256>>>(W3, w3_h, w3_l, DMODEL, DFFN);
    wsplit_kernel<<<dim3(DMODEL/32, DFFN/32),   256>>>(W2, w2_h, w2_l, DFFN, DMODEL);

    // 1. norm1 (+ split)
    rmsnorm_split_kernel<<<M, 256>>>(x, norm1_w, xn_h, xn_l);
    // 2. Q, K, V projections
    gemm_bf16x3<<<gD, 256, GEMM_SMEM>>>(xn_h, xn_l, wq_h, wq_l, nullptr, p_q, DMODEL, DMODEL);
    gemm_bf16x3<<<gD, 256, GEMM_SMEM>>>(xn_h, xn_l, wk_h, wk_l, nullptr, p_k, DMODEL, DMODEL);
    gemm_bf16x3<<<gD, 256, GEMM_SMEM>>>(xn_h, xn_l, wv_h, wv_l, nullptr, p_v, DMODEL, DMODEL);
    // 3. windowed attention (+ split)
    attn_kernel<<<M, 256>>>(p_q, p_k, p_v, att_h, att_l);
    // 4. x_mid = x + attended @ Wo
    gemm_bf16x3<<<gD, 256, GEMM_SMEM>>>(att_h, att_l, wo_h, wo_l, x, p_xmid, DMODEL, DMODEL);
    // 5. norm2 (+ split)
    rmsnorm_split_kernel<<<M, 256>>>(p_xmid, norm2_w, xn2_h, xn2_l);
    // 6. FFN up projections
    gemm_bf16x3<<<gF, 256, GEMM_SMEM>>>(xn2_h, xn2_l, w1_h, w1_l, nullptr, p_h1, DFFN, DMODEL);
    gemm_bf16x3<<<gF, 256, GEMM_SMEM>>>(xn2_h, xn2_l, w3_h, w3_l, nullptr, p_h3, DFFN, DMODEL);
    // 7. gate = silu(h1) * h3 (+ split)
    {
        int n4 = M * DFFN / 4;
        swiglu_split_kernel<<<(n4 + 255) / 256, 256>>>(p_h1, p_h3, gate_h, gate_l, n4);
    }
    // 8. out = x_mid + gate @ W2
    gemm_bf16x3<<<gD, 256, GEMM_SMEM>>>(gate_h, gate_l, w2_h, w2_l, p_xmid, out, DMODEL, DFFN);
}

// round 4
// speedup vs baseline: 1.9229x; 1.0640x over previous
#include <cuda_runtime.h>
#include <cuda_bf16.h>
#include <cstdint>
#include <math.h>

// Problem constants
#define BATCH 4
#define SEQ   2048
#define DMODEL 1024
#define DFFN  2048
#define WIN   64
#define MROWS (BATCH*SEQ)   // 8192
#define EPS   1e-6f

// ---------------- scratch (device globals; no allocation allowed) -------------
__device__ float g_qkv [MROWS * 3 * DMODEL];   // fused [M, 3072]: q|k|v
__device__ float g_xmid[MROWS * DMODEL];
__device__ float g_h13 [MROWS * 2 * DFFN];     // fused [M, 4096]: h1|h3
// bf16 split activations (A operands, [M,K])
__device__ __nv_bfloat16 g_xn_h [MROWS * DMODEL];
__device__ __nv_bfloat16 g_xn_l [MROWS * DMODEL];
__device__ __nv_bfloat16 g_att_h[MROWS * DMODEL];
__device__ __nv_bfloat16 g_att_l[MROWS * DMODEL];
__device__ __nv_bfloat16 g_xn2_h[MROWS * DMODEL];
__device__ __nv_bfloat16 g_xn2_l[MROWS * DMODEL];
__device__ __nv_bfloat16 g_gate_h[MROWS * DFFN];
__device__ __nv_bfloat16 g_gate_l[MROWS * DFFN];
// bf16 split + transposed weights [N,K]; fused along N
__device__ __nv_bfloat16 g_wqkv_h[3 * DMODEL * DMODEL];
__device__ __nv_bfloat16 g_wqkv_l[3 * DMODEL * DMODEL];
__device__ __nv_bfloat16 g_wo_h[DMODEL * DMODEL];
__device__ __nv_bfloat16 g_wo_l[DMODEL * DMODEL];
__device__ __nv_bfloat16 g_w13_h[2 * DFFN * DMODEL];
__device__ __nv_bfloat16 g_w13_l[2 * DFFN * DMODEL];
__device__ __nv_bfloat16 g_w2_h[DMODEL * DFFN];
__device__ __nv_bfloat16 g_w2_l[DMODEL * DFFN];

// ============================= PTX helpers ====================================
__device__ __forceinline__ uint32_t smem_u32(const void* p) {
    uint32_t a;
    asm("{ .reg .u64 t; cvta.to.shared.u64 t, %1; cvt.u32.u64 %0, t; }"
        : "=r"(a) : "l"(p));
    return a;
}
__device__ __forceinline__ uint32_t swz128(uint32_t o) {
    return o ^ ((o >> 3) & 0x70);
}
__device__ __forceinline__ void cpasync16(uint32_t dst, const void* src) {
    asm volatile("cp.async.cg.shared.global [%0], [%1], 16;"
                 :: "r"(dst), "l"(__cvta_generic_to_global(src)) : "memory");
}
__device__ __forceinline__ void cp_commit() {
    asm volatile("cp.async.commit_group;" ::: "memory");
}
template <int N>
__device__ __forceinline__ void cp_wait() {
    asm volatile("cp.async.wait_group %0;" :: "n"(N) : "memory");
}
__device__ __forceinline__ void ldsm_x4(uint32_t* r, uint32_t addr) {
    asm volatile("ldmatrix.sync.aligned.m8n8.x4.shared.b16 {%0,%1,%2,%3}, [%4];"
                 : "=r"(r[0]), "=r"(r[1]), "=r"(r[2]), "=r"(r[3]) : "r"(addr));
}
__device__ __forceinline__ void mma16816(float* c, const uint32_t* a,
                                         uint32_t b0, uint32_t b1) {
    asm volatile(
        "mma.sync.aligned.m16n8k16.row.col.f32.bf16.bf16.f32 "
        "{%0,%1,%2,%3}, {%4,%5,%6,%7}, {%8,%9}, {%0,%1,%2,%3};"
        : "+f"(c[0]), "+f"(c[1]), "+f"(c[2]), "+f"(c[3])
        : "r"(a[0]), "r"(a[1]), "r"(a[2]), "r"(a[3]), "r"(b0), "r"(b1));
}

// ====================== bf16x3 GEMM via mma.sync ==============================
// C[M,N] = (Ah+Al)[M,K] @ (Bh+Bl)[N,K]^T (+R), fp32 out.
// Tile 128x128, BK=64, 256 threads (8 warps, 4x2), 3-stage cp.async pipeline.
#define GBM 128
#define GBN 128
#define GBK 64
#define NSTAGE 3
#define AH_OFF 0
#define AL_OFF 16384
#define BH_OFF 32768
#define BL_OFF 49152
#define STAGE_BYTES 65536
#define GEMM_SMEM (NSTAGE * STAGE_BYTES)

__device__ __forceinline__ void gemm_load_stage(
    uint32_t sb,
    const __nv_bfloat16* __restrict__ Ah, const __nv_bfloat16* __restrict__ Al,
    const __nv_bfloat16* __restrict__ Bh, const __nv_bfloat16* __restrict__ Bl,
    int m0, int n0, int k0, int K, int tid)
{
    const int row  = tid >> 1;            // 0..127
    const int half = (tid & 1) * 64;      // byte offset within 128B row
    const uint32_t so = row * 128 + half;

    const char* pAh = (const char*)(Ah + (size_t)(m0 + row) * K + k0) + half;
    const char* pAl = (const char*)(Al + (size_t)(m0 + row) * K + k0) + half;
    const char* pBh = (const char*)(Bh + (size_t)(n0 + row) * K + k0) + half;
    const char* pBl = (const char*)(Bl + (size_t)(n0 + row) * K + k0) + half;

    #pragma unroll
    for (int s = 0; s < 4; ++s) {
        uint32_t d = swz128(so + s * 16);
        cpasync16(sb + AH_OFF + d, pAh + s * 16);
        cpasync16(sb + AL_OFF + d, pAl + s * 16);
        cpasync16(sb + BH_OFF + d, pBh + s * 16);
        cpasync16(sb + BL_OFF + d, pBl + s * 16);
    }
}

__global__ __launch_bounds__(256, 1)
void gemm_bf16x3(const __nv_bfloat16* __restrict__ Ah, const __nv_bfloat16* __restrict__ Al,
                 const __nv_bfloat16* __restrict__ Bh, const __nv_bfloat16* __restrict__ Bl,
                 const float* __restrict__ R, float* __restrict__ C,
                 int N, int K)
{
    extern __shared__ char smem[];
    const int tid  = threadIdx.x;
    const int wid  = tid >> 5;
    const int lane = tid & 31;
    const int m0 = blockIdx.y * GBM;
    const int n0 = blockIdx.x * GBN;
    const int nk = K / GBK;

    const uint32_t base = smem_u32(smem);
    const int wm0 = (wid & 3) * 32;   // warp row offset in tile
    const int wn0 = (wid >> 2) * 64;  // warp col offset in tile

    float acc[2][8][4];
    #pragma unroll
    for (int i = 0; i < 2; ++i)
        #pragma unroll
        for (int j = 0; j < 8; ++j)
            #pragma unroll
            for (int t = 0; t < 4; ++t) acc[i][j][t] = 0.0f;

    // prologue: stages 0..NSTAGE-2
    #pragma unroll
    for (int p = 0; p < NSTAGE - 1; ++p) {
        gemm_load_stage(base + p * STAGE_BYTES, Ah, Al, Bh, Bl, m0, n0, p * GBK, K, tid);
        cp_commit();
    }

    const uint32_t lrow  = (lane & 15);
    const uint32_t lkoff = (lane >> 4) << 4;

    for (int i = 0; i < nk; ++i) {
        cp_wait<NSTAGE - 2>();
        __syncthreads();           // all warps done with stage (i-1) buffer

        // issue next stage loads EARLY (into buffer freed at last iteration)
        const int nc = i + NSTAGE - 1;
        if (nc < nk)
            gemm_load_stage(base + (nc % NSTAGE) * STAGE_BYTES,
                            Ah, Al, Bh, Bl, m0, n0, nc * GBK, K, tid);
        cp_commit();   // uniform commit keeps wait_group arithmetic exact

        const uint32_t sb = base + (i % NSTAGE) * STAGE_BYTES;
        #pragma unroll
        for (int ks = 0; ks < 4; ++ks) {
            uint32_t ah[2][4], al[2][4], bh[4][4], bl[4][4];
            #pragma unroll
            for (int ma = 0; ma < 2; ++ma) {
                uint32_t off = (wm0 + ma * 16 + lrow) * 128 + ks * 32 + lkoff;
                uint32_t ad = sb + swz128(off);
                ldsm_x4(ah[ma], ad + AH_OFF);
                ldsm_x4(al[ma], ad + AL_OFF);
            }
            #pragma unroll
            for (int ng = 0; ng < 4; ++ng) {
                uint32_t off = (wn0 + ng * 16 + lrow) * 128 + ks * 32 + lkoff;
                uint32_t bd = sb + swz128(off);
                ldsm_x4(bh[ng], bd + BH_OFF);
                ldsm_x4(bl[ng], bd + BL_OFF);
            }
            #pragma unroll
            for (int ma = 0; ma < 2; ++ma)
                #pragma unroll
                for (int ng = 0; ng < 4; ++ng)
                    #pragma unroll
                    for (int h = 0; h < 2; ++h) {
                        const int na = ng * 2 + h;
                        mma16816(acc[ma][na], ah[ma], bh[ng][h], bh[ng][2 + h]);
                        mma16816(acc[ma][na], ah[ma], bl[ng][h], bl[ng][2 + h]);
                        mma16816(acc[ma][na], al[ma], bh[ng][h], bh[ng][2 + h]);
                    }
        }
        // no trailing sync: next iteration's barrier protects buffer reuse
    }

    // epilogue: direct stores (float2), optional residual
    const int mrow = lane >> 2;          // 0..7
    const int ncol = (lane & 3) * 2;
    #pragma unroll
    for (int ma = 0; ma < 2; ++ma) {
        #pragma unroll
        for (int na = 0; na < 8; ++na) {
            const int m = m0 + wm0 + ma * 16 + mrow;
            const int n = n0 + wn0 + na * 8 + ncol;
            size_t o0 = (size_t)m * N + n;
            size_t o1 = o0 + (size_t)8 * N;
            float2 v0 = make_float2(acc[ma][na][0], acc[ma][na][1]);
            float2 v1 = make_float2(acc[ma][na][2], acc[ma][na][3]);
            if (R) {
                float2 r0 = *reinterpret_cast<const float2*>(R + o0);
                float2 r1 = *reinterpret_cast<const float2*>(R + o1);
                v0.x += r0.x; v0.y += r0.y;
                v1.x += r1.x; v1.y += r1.y;
            }
            *reinterpret_cast<float2*>(C + o0) = v0;
            *reinterpret_cast<float2*>(C + o1) = v1;
        }
    }
}

// ================= weight transpose + bf16 split: [K,N]f32 -> [N,K]bf16 x2 ====
__global__ void wsplit_kernel(const float* __restrict__ W,
                              __nv_bfloat16* __restrict__ Th,
                              __nv_bfloat16* __restrict__ Tl,
                              int K, int N)
{
    __shared__ float t[32][33];
    int n0 = blockIdx.x * 32, k0 = blockIdx.y * 32;
    int tx = threadIdx.x & 31, ty = threadIdx.x >> 5;   // 256 thr: ty 0..7
    #pragma unroll
    for (int r = ty; r < 32; r += 8)
        t[r][tx] = W[(size_t)(k0 + r) * N + n0 + tx];
    __syncthreads();
    #pragma unroll
    for (int r = ty; r < 32; r += 8) {
        float v = t[tx][r];                       // W[k0+tx][n0+r]
        __nv_bfloat16 h = __float2bfloat16(v);
        __nv_bfloat16 l = __float2bfloat16(v - __bfloat162float(h));
        size_t o = (size_t)(n0 + r) * K + k0 + tx;
        Th[o] = h; Tl[o] = l;
    }
}

// ---------------- RMSNorm + bf16 split ----------------------------------------
__global__ void rmsnorm_split_kernel(const float* __restrict__ x,
                                     const float* __restrict__ w,
                                     __nv_bfloat16* __restrict__ oh,
                                     __nv_bfloat16* __restrict__ ol) {
    const int D = DMODEL;
    size_t row = blockIdx.x;
    const float4* xr = reinterpret_cast<const float4*>(x + row * D);
    const float4* wr = reinterpret_cast<const float4*>(w);

    int tid = threadIdx.x;
    float4 xv = xr[tid];
    float ss = xv.x*xv.x + xv.y*xv.y + xv.z*xv.z + xv.w*xv.w;
    #pragma unroll
    for (int off = 16; off; off >>= 1)
        ss += __shfl_xor_sync(0xffffffffu, ss, off);
    __shared__ float red[8];
    int lane = tid & 31, warp = tid >> 5;
    if (lane == 0) red[warp] = ss;
    __syncthreads();
    if (tid < 32) {
        float v = (tid < 8) ? red[tid] : 0.0f;
        #pragma unroll
        for (int off = 4; off; off >>= 1)
            v += __shfl_xor_sync(0xffffffffu, v, off);
        if (tid == 0) red[0] = rsqrtf(v * (1.0f / D) + EPS);
    }
    __syncthreads();
    float inv = red[0];
    float4 wv = wr[tid];
    float f[4];
    f[0] = xv.x * inv * wv.x; f[1] = xv.y * inv * wv.y;
    f[2] = xv.z * inv * wv.z; f[3] = xv.w * inv * wv.w;

    alignas(8) __nv_bfloat16 hv[4], lv[4];
    #pragma unroll
    for (int j = 0; j < 4; ++j) {
        hv[j] = __float2bfloat16(f[j]);
        lv[j] = __float2bfloat16(f[j] - __bfloat162float(hv[j]));
    }
    size_t b = row * D + tid * 4;
    *reinterpret_cast<uint2*>(oh + b) = *reinterpret_cast<uint2*>(hv);
    *reinterpret_cast<uint2*>(ol + b) = *reinterpret_cast<uint2*>(lv);
}

// ---------------- Tiled windowed causal attention -----------------------------
// 64 queries per block; K/V span (<=127 rows) streamed through smem in chunks.
// q/k/v read from fused qkv buffer [M, 3072] (col offsets 0/1024/2048).
#define ATQ  64
#define SPAD 129
#define KPAD 68
#define VPAD 132
#define S_FLOATS (64 * SPAD)                       // 8256
#define SCR_FLOATS (128 * VPAD)                    // 16896 > 64*KPAD + 128*KPAD = 13056
#define ATTN_SMEM ((S_FLOATS + SCR_FLOATS) * 4)    // 100608 B

__global__ __launch_bounds__(256, 1)
void attn_tile_kernel(const float* __restrict__ qkv,
                      __nv_bfloat16* __restrict__ oh,
                      __nv_bfloat16* __restrict__ ol)
{
    extern __shared__ float sm[];
    float* S   = sm;                 // [64][SPAD]
    float* scr = sm + S_FLOATS;
    float* Qc  = scr;                // [64][KPAD]   (phase 1)
    float* Kc  = scr + 64 * KPAD;    // [128][KPAD]  (phase 1)
    float* Vc  = scr;                // [128][VPAD]  (phase 2)

    const int tid  = threadIdx.x;
    const int ty   = tid >> 5;
    const int lane = tid & 31;
    const int blk  = blockIdx.x;
    const int b    = blk >> 5;               // 32 tiles per batch
    const int t0   = (blk & 31) * ATQ;
    const int jlo  = (t0 == 0) ? 0 : t0 - (WIN - 1);
    const int span = t0 + ATQ - jlo;         // <= 127
    const size_t rowbase = (size_t)b * SEQ;
    const float scale = 0.03125f;

    const int qi0 = ty * 8;
    const int bs  = (t0 == 0) ? 0 : qi0;     // band start of this warp's queries

    // zero S
    for (int i = tid; i < S_FLOATS; i += 256) S[i] = 0.0f;

    // clamped key slots for this lane (3 slots cover band width <=96)
    int kkc[3];
    #pragma unroll
    for (int r = 0; r < 3; ++r) {
        int kk = bs + lane + 32 * r;
        kkc[r] = kk < 128 ? kk : 127;
    }

    float acc[8][3];
    #pragma unroll
    for (int q = 0; q < 8; ++q)
        #pragma unroll
        for (int r = 0; r < 3; ++r) acc[q][r] = 0.0f;

    // ---- phase 1: scores over 16 d-chunks of 64 ----
    for (int dc = 0; dc < 16; ++dc) {
        const int d0 = dc * 64;
        {   // load Qc [64][64]
            int r = tid >> 2, c0 = (tid & 3) * 16;
            const float* src = qkv + (rowbase + t0 + r) * 3072 + d0 + c0;
            float* dst = Qc + r * KPAD + c0;
            #pragma unroll
            for (int s = 0; s < 4; ++s)
                *reinterpret_cast<float4*>(dst + s * 4) =
                    *reinterpret_cast<const float4*>(src + s * 4);
        }
        {   // load Kc [span][64]
            int r = tid >> 1, c0 = (tid & 1) * 32;
            if (r < span) {
                const float* src = qkv + (rowbase + jlo + r) * 3072 + 1024 + d0 + c0;
                float* dst = Kc + r * KPAD + c0;
                #pragma unroll
                for (int s = 0; s < 8; ++s)
                    *reinterpret_cast<float4*>(dst + s * 4) =
                        *reinterpret_cast<const float4*>(src + s * 4);
            }
        }
        __syncthreads();

        #pragma unroll 4
        for (int d4 = 0; d4 < 64; d4 += 4) {
            float4 kf[3];
            #pragma unroll
            for (int r = 0; r < 3; ++r)
                kf[r] = *reinterpret_cast<const float4*>(Kc + kkc[r] * KPAD + d4);
            #pragma unroll
            for (int q = 0; q < 8; ++q) {
                float4 qf = *reinterpret_cast<const float4*>(Qc + (qi0 + q) * KPAD + d4);
                #pragma unroll
                for (int r = 0; r < 3; ++r) {
                    acc[q][r] = fmaf(qf.x, kf[r].x, acc[q][r]);
                    acc[q][r] = fmaf(qf.y, kf[r].y, acc[q][r]);
                    acc[q][r] = fmaf(qf.z, kf[r].z, acc[q][r]);
                    acc[q][r] = fmaf(qf.w, kf[r].w, acc[q][r]);
                }
            }
        }
        __syncthreads();
    }

    // write band scores to S (invalid entries fixed by softmax phase)
    #pragma unroll
    for (int q = 0; q < 8; ++q)
        #pragma unroll
        for (int r = 0; r < 3; ++r) {
            int kk = bs + lane + 32 * r;
            if (kk < 128) S[(qi0 + q) * SPAD + kk] = acc[q][r] * scale;
        }
    __syncthreads();

    // ---- phase 2: softmax (one thread per query) ----
    if (tid < ATQ) {
        const int qi  = tid;
        const int ti  = t0 + qi;
        const int wlo = ((ti >= WIN - 1) ? ti - (WIN - 1) : 0) - jlo;
        const int whi = ti - jlo;
        float* row = S + qi * SPAD;
        float m = -1e30f;
        for (int jj = wlo; jj <= whi; ++jj) m = fmaxf(m, row[jj]);
        float sum = 0.0f;
        for (int jj = wlo; jj <= whi; ++jj) {
            float e = __expf(row[jj] - m);
            row[jj] = e;
            sum += e;
        }
        float inv = 1.0f / sum;
        for (int jj = 0; jj < SPAD; ++jj)
            row[jj] = (jj >= wlo && jj <= whi) ? row[jj] * inv : 0.0f;
    }
    __syncthreads();

    // ---- phase 3: PV over 8 d-chunks of 128 ----
    const int js = (t0 == 0) ? 0 : qi0;
    const int je = (t0 == 0) ? (qi0 + 7) : (qi0 + 70);   // inclusive; <= span-1
    for (int vc = 0; vc < 8; ++vc) {
        const int d0 = vc * 128;
        {   // load Vc [span][128]
            int r = tid >> 1, c0 = (tid & 1) * 64;
            if (r < span) {
                const float* src = qkv + (rowbase + jlo + r) * 3072 + 2048 + d0 + c0;
                float* dst = Vc + r * VPAD + c0;
                #pragma unroll
                for (int s = 0; s < 16; ++s)
                    *reinterpret_cast<float4*>(dst + s * 4) =
                        *reinterpret_cast<const float4*>(src + s * 4);
            }
        }
        __syncthreads();

        float4 out[8];
        #pragma unroll
        for (int q = 0; q < 8; ++q) out[q] = make_float4(0.f, 0.f, 0.f, 0.f);

        for (int jj = js; jj <= je; ++jj) {
            float4 v = *reinterpret_cast<const float4*>(Vc + jj * VPAD + lane * 4);
            #pragma unroll
            for (int q = 0; q < 8; ++q) {
                float w = S[(qi0 + q) * SPAD + jj];
                out[q].x = fmaf(w, v.x, out[q].x);
                out[q].y = fmaf(w, v.y, out[q].y);
                out[q].z = fmaf(w, v.z, out[q].z);
                out[q].w = fmaf(w, v.w, out[q].w);
            }
        }

        #pragma unroll
        for (int q = 0; q < 8; ++q) {
            size_t o = (rowbase + t0 + qi0 + q) * DMODEL + d0 + lane * 4;
            float f[4] = {out[q].x, out[q].y, out[q].z, out[q].w};
            alignas(8) __nv_bfloat16 hv[4], lv[4];
            #pragma unroll
            for (int j = 0; j < 4; ++j) {
                hv[j] = __float2bfloat16(f[j]);
                lv[j] = __float2bfloat16(f[j] - __bfloat162float(hv[j]));
            }
            *reinterpret_cast<uint2*>(oh + o) = *reinterpret_cast<uint2*>(hv);
            *reinterpret_cast<uint2*>(ol + o) = *reinterpret_cast<uint2*>(lv);
        }
        __syncthreads();
    }
}

// ---------------- SwiGLU + bf16 split (fused h13 input) ------------------------
__global__ void swiglu_split_kernel(const float* __restrict__ h13,
                                    __nv_bfloat16* __restrict__ gh,
                                    __nv_bfloat16* __restrict__ gl, int n4) {
    int idx = blockIdx.x * blockDim.x + threadIdx.x;
    if (idx >= n4) return;
    int row = idx >> 9;               // DFFN/4 = 512 groups per row
    int cg  = idx & 511;
    const float* base = h13 + (size_t)row * (2 * DFFN) + cg * 4;
    float4 a = *reinterpret_cast<const float4*>(base);
    float4 c = *reinterpret_cast<const float4*>(base + DFFN);
    float f[4];
    f[0] = a.x / (1.0f + __expf(-a.x)) * c.x;
    f[1] = a.y / (1.0f + __expf(-a.y)) * c.y;
    f[2] = a.z / (1.0f + __expf(-a.z)) * c.z;
    f[3] = a.w / (1.0f + __expf(-a.w)) * c.w;
    alignas(8) __nv_bfloat16 hv[4], lv[4];
    #pragma unroll
    for (int j = 0; j < 4; ++j) {
        hv[j] = __float2bfloat16(f[j]);
        lv[j] = __float2bfloat16(f[j] - __bfloat162float(hv[j]));
    }
    size_t o = (size_t)row * DFFN + cg * 4;
    *reinterpret_cast<uint2*>(gh + o) = *reinterpret_cast<uint2*>(hv);
    *reinterpret_cast<uint2*>(gl + o) = *reinterpret_cast<uint2*>(lv);
}

// ---------------- launch -------------------------------------------------------
extern "C" void kernel_launch(void* const* d_in, const int* in_sizes, int n_in,
                              void* d_out, int out_size) {
    const float* x       = (const float*)d_in[0];
    const float* norm1_w = (const float*)d_in[1];
    const float* norm2_w = (const float*)d_in[2];
    const float* Wq      = (const float*)d_in[3];
    const float* Wk      = (const float*)d_in[4];
    const float* Wv      = (const float*)d_in[5];
    const float* Wo      = (const float*)d_in[6];
    const float* W1      = (const float*)d_in[7];
    const float* W2      = (const float*)d_in[8];
    const float* W3      = (const float*)d_in[9];
    float* out = (float*)d_out;

    float *p_qkv, *p_xmid, *p_h13;
    cudaGetSymbolAddress((void**)&p_qkv,  g_qkv);
    cudaGetSymbolAddress((void**)&p_xmid, g_xmid);
    cudaGetSymbolAddress((void**)&p_h13,  g_h13);

    __nv_bfloat16 *xn_h, *xn_l, *att_h, *att_l, *xn2_h, *xn2_l, *gate_h, *gate_l;
    cudaGetSymbolAddress((void**)&xn_h,  g_xn_h);
    cudaGetSymbolAddress((void**)&xn_l,  g_xn_l);
    cudaGetSymbolAddress((void**)&att_h, g_att_h);
    cudaGetSymbolAddress((void**)&att_l, g_att_l);
    cudaGetSymbolAddress((void**)&xn2_h, g_xn2_h);
    cudaGetSymbolAddress((void**)&xn2_l, g_xn2_l);
    cudaGetSymbolAddress((void**)&gate_h, g_gate_h);
    cudaGetSymbolAddress((void**)&gate_l, g_gate_l);

    __nv_bfloat16 *wqkv_h, *wqkv_l, *wo_h, *wo_l, *w13_h, *w13_l, *w2_h, *w2_l;
    cudaGetSymbolAddress((void**)&wqkv_h, g_wqkv_h);
    cudaGetSymbolAddress((void**)&wqkv_l, g_wqkv_l);
    cudaGetSymbolAddress((void**)&wo_h, g_wo_h);
    cudaGetSymbolAddress((void**)&wo_l, g_wo_l);
    cudaGetSymbolAddress((void**)&w13_h, g_w13_h);
    cudaGetSymbolAddress((void**)&w13_l, g_w13_l);
    cudaGetSymbolAddress((void**)&w2_h, g_w2_h);
    cudaGetSymbolAddress((void**)&w2_l, g_w2_l);

    cudaFuncSetAttribute(gemm_bf16x3, cudaFuncAttributeMaxDynamicSharedMemorySize, GEMM_SMEM);
    cudaFuncSetAttribute(attn_tile_kernel, cudaFuncAttributeMaxDynamicSharedMemorySize, ATTN_SMEM);

    const int M = MROWS;                 // 8192
    const int DD = DMODEL * DMODEL;      // 1M elements per weight section
    dim3 gQKV(3 * DMODEL / GBN, M / GBM);   // (24, 64)
    dim3 gD  (DMODEL / GBN,     M / GBM);   // (8, 64)
    dim3 gF13(2 * DFFN / GBN,   M / GBM);   // (32, 64)

    // weight transpose + split into fused buffers
    wsplit_kernel<<<dim3(DMODEL/32, DMODEL/32), 256>>>(Wq, wqkv_h,          wqkv_l,          DMODEL, DMODEL);
    wsplit_kernel<<<dim3(DMODEL/32, DMODEL/32), 256>>>(Wk, wqkv_h + DD,     wqkv_l + DD,     DMODEL, DMODEL);
    wsplit_kernel<<<dim3(DMODEL/32, DMODEL/32), 256>>>(Wv, wqkv_h + 2*DD,   wqkv_l + 2*DD,   DMODEL, DMODEL);
    wsplit_kernel<<<dim3(DMODEL/32, DMODEL/32), 256>>>(Wo, wo_h,            wo_l,            DMODEL, DMODEL);
    wsplit_kernel<<<dim3(DFFN/32,   DMODEL/32), 256>>>(W1, w13_h,           w13_l,           DMODEL, DFFN);
    wsplit_kernel<<<dim3(DFFN/32,   DMODEL/32), 256>>>(W3, w13_h + DFFN*DMODEL, w13_l + DFFN*DMODEL, DMODEL, DFFN);
    wsplit_kernel<<<dim3(DMODEL/32, DFFN/32),   256>>>(W2, w2_h,            w2_l,            DFFN, DMODEL);

    // 1. norm1 (+ split)
    rmsnorm_split_kernel<<<M, 256>>>(x, norm1_w, xn_h, xn_l);
    // 2. fused QKV projection -> [M, 3072]
    gemm_bf16x3<<<gQKV, 256, GEMM_SMEM>>>(xn_h, xn_l, wqkv_h, wqkv_l, nullptr, p_qkv, 3*DMODEL, DMODEL);
    // 3. tiled windowed attention (+ split)
    attn_tile_kernel<<<M / ATQ, 256, ATTN_SMEM>>>(p_qkv, att_h, att_l);
    // 4. x_mid = x + attended @ Wo
    gemm_bf16x3<<<gD, 256, GEMM_SMEM>>>(att_h, att_l, wo_h, wo_l, x, p_xmid, DMODEL, DMODEL);
    // 5. norm2 (+ split)
    rmsnorm_split_kernel<<<M, 256>>>(p_xmid, norm2_w, xn2_h, xn2_l);
    // 6. fused FFN up projection -> [M, 4096]
    gemm_bf16x3<<<gF13, 256, GEMM_SMEM>>>(xn2_h, xn2_l, w13_h, w13_l, nullptr, p_h13, 2*DFFN, DMODEL);
    // 7. gate = silu(h1) * h3 (+ split)
    {
        int n4 = M * DFFN / 4;
        swiglu_split_kernel<<<(n4 + 255) / 256, 256>>>(p_h13, gate_h, gate_l, n4);
    }
    // 8. out = x_mid + gate @ W2
    gemm_bf16x3<<<gD, 256, GEMM_SMEM>>>(gate_h, gate_l, w2_h, w2_l, p_xmid, out, DMODEL, DFFN);
}

// round 5
// speedup vs baseline: 2.6029x; 1.3536x over previous
#include <cuda_runtime.h>
#include <cuda_fp16.h>
#include <cstdint>
#include <math.h>

// Problem constants
#define BATCH 4
#define SEQ   2048
#define DMODEL 1024
#define DFFN  2048
#define WIN   64
#define MROWS (BATCH*SEQ)   // 8192
#define EPS   1e-6f

// ---------------- scratch (device globals; no allocation allowed) -------------
__device__ float g_qkv [MROWS * 3 * DMODEL];   // fused [M, 3072]: q|k|v
__device__ float g_xmid[MROWS * DMODEL];
__device__ float g_h13 [MROWS * 2 * DFFN];     // fused [M, 4096]: h1|h3
// fp16 split activations (A operands, [M,K])
__device__ __half g_xn_h [MROWS * DMODEL];
__device__ __half g_xn_l [MROWS * DMODEL];
__device__ __half g_att_h[MROWS * DMODEL];
__device__ __half g_att_l[MROWS * DMODEL];
__device__ __half g_xn2_h[MROWS * DMODEL];
__device__ __half g_xn2_l[MROWS * DMODEL];
__device__ __half g_gate_h[MROWS * DFFN];
__device__ __half g_gate_l[MROWS * DFFN];
// fp16 transposed weights [N,K]; fused along N
__device__ __half g_wqkv[3 * DMODEL * DMODEL];
__device__ __half g_wo  [DMODEL * DMODEL];
__device__ __half g_w13 [2 * DFFN * DMODEL];
__device__ __half g_w2  [DMODEL * DFFN];

// ============================= PTX helpers ====================================
__device__ __forceinline__ uint32_t smem_u32(const void* p) {
    uint32_t a;
    asm("{ .reg .u64 t; cvta.to.shared.u64 t, %1; cvt.u32.u64 %0, t; }"
        : "=r"(a) : "l"(p));
    return a;
}
__device__ __forceinline__ uint32_t swz128(uint32_t o) {
    return o ^ ((o >> 3) & 0x70);
}
__device__ __forceinline__ void cpasync16(uint32_t dst, const void* src) {
    asm volatile("cp.async.cg.shared.global [%0], [%1], 16;"
                 :: "r"(dst), "l"(__cvta_generic_to_global(src)) : "memory");
}
__device__ __forceinline__ void cp_commit() {
    asm volatile("cp.async.commit_group;" ::: "memory");
}
template <int N>
__device__ __forceinline__ void cp_wait() {
    asm volatile("cp.async.wait_group %0;" :: "n"(N) : "memory");
}
__device__ __forceinline__ void ldsm_x4(uint32_t* r, uint32_t addr) {
    asm volatile("ldmatrix.sync.aligned.m8n8.x4.shared.b16 {%0,%1,%2,%3}, [%4];"
                 : "=r"(r[0]), "=r"(r[1]), "=r"(r[2]), "=r"(r[3]) : "r"(addr));
}
__device__ __forceinline__ void mma16816(float* c, const uint32_t* a,
                                         uint32_t b0, uint32_t b1) {
    asm volatile(
        "mma.sync.aligned.m16n8k16.row.col.f32.f16.f16.f32 "
        "{%0,%1,%2,%3}, {%4,%5,%6,%7}, {%8,%9}, {%0,%1,%2,%3};"
        : "+f"(c[0]), "+f"(c[1]), "+f"(c[2]), "+f"(c[3])
        : "r"(a[0]), "r"(a[1]), "r"(a[2]), "r"(a[3]), "r"(b0), "r"(b1));
}

// ====================== fp16x2 GEMM via mma.sync ==============================
// C[M,N] = (Ah+Al)[M,K] @ Bh[N,K]^T (+R), fp32 out.
// Tile 128x128, BK=64, 256 threads (8 warps, 4x2), 4-stage cp.async pipeline.
#define GBM 128
#define GBN 128
#define GBK 64
#define NSTAGE 4
#define AH_OFF 0
#define AL_OFF 16384
#define BH_OFF 32768
#define STAGE_BYTES 49152
#define GEMM_SMEM (NSTAGE * STAGE_BYTES)   // 196608

__device__ __forceinline__ void gemm_load_stage(
    uint32_t sb,
    const __half* __restrict__ Ah, const __half* __restrict__ Al,
    const __half* __restrict__ Bh,
    int m0, int n0, int k0, int K, int tid)
{
    const int row  = tid >> 1;            // 0..127
    const int half = (tid & 1) * 64;      // byte offset within 128B row
    const uint32_t so = row * 128 + half;

    const char* pAh = (const char*)(Ah + (size_t)(m0 + row) * K + k0) + half;
    const char* pAl = (const char*)(Al + (size_t)(m0 + row) * K + k0) + half;
    const char* pBh = (const char*)(Bh + (size_t)(n0 + row) * K + k0) + half;

    #pragma unroll
    for (int s = 0; s < 4; ++s) {
        uint32_t d = swz128(so + s * 16);
        cpasync16(sb + AH_OFF + d, pAh + s * 16);
        cpasync16(sb + AL_OFF + d, pAl + s * 16);
        cpasync16(sb + BH_OFF + d, pBh + s * 16);
    }
}

__global__ __launch_bounds__(256, 1)
void gemm_fp16x2(const __half* __restrict__ Ah, const __half* __restrict__ Al,
                 const __half* __restrict__ Bh,
                 const float* __restrict__ R, float* __restrict__ C,
                 int N, int K)
{
    extern __shared__ char smem[];
    const int tid  = threadIdx.x;
    const int wid  = tid >> 5;
    const int lane = tid & 31;
    const int m0 = blockIdx.y * GBM;
    const int n0 = blockIdx.x * GBN;
    const int nk = K / GBK;

    const uint32_t base = smem_u32(smem);
    const int wm0 = (wid & 3) * 32;   // warp row offset in tile
    const int wn0 = (wid >> 2) * 64;  // warp col offset in tile

    float acc[2][8][4];
    #pragma unroll
    for (int i = 0; i < 2; ++i)
        #pragma unroll
        for (int j = 0; j < 8; ++j)
            #pragma unroll
            for (int t = 0; t < 4; ++t) acc[i][j][t] = 0.0f;

    // prologue: stages 0..NSTAGE-2
    #pragma unroll
    for (int p = 0; p < NSTAGE - 1; ++p) {
        gemm_load_stage(base + p * STAGE_BYTES, Ah, Al, Bh, m0, n0, p * GBK, K, tid);
        cp_commit();
    }

    const uint32_t lrow  = (lane & 15);
    const uint32_t lkoff = (lane >> 4) << 4;

    for (int i = 0; i < nk; ++i) {
        cp_wait<NSTAGE - 2>();
        __syncthreads();           // all warps done with old buffer

        // issue next stage loads EARLY
        const int nc = i + NSTAGE - 1;
        if (nc < nk)
            gemm_load_stage(base + (nc % NSTAGE) * STAGE_BYTES,
                            Ah, Al, Bh, m0, n0, nc * GBK, K, tid);
        cp_commit();   // uniform commit keeps wait_group arithmetic exact

        const uint32_t sb = base + (i % NSTAGE) * STAGE_BYTES;
        #pragma unroll
        for (int ks = 0; ks < 4; ++ks) {
            uint32_t ah[2][4], al[2][4], bh[4][4];
            #pragma unroll
            for (int ma = 0; ma < 2; ++ma) {
                uint32_t off = (wm0 + ma * 16 + lrow) * 128 + ks * 32 + lkoff;
                uint32_t ad = sb + swz128(off);
                ldsm_x4(ah[ma], ad + AH_OFF);
                ldsm_x4(al[ma], ad + AL_OFF);
            }
            #pragma unroll
            for (int ng = 0; ng < 4; ++ng) {
                uint32_t off = (wn0 + ng * 16 + lrow) * 128 + ks * 32 + lkoff;
                ldsm_x4(bh[ng], sb + BH_OFF + swz128(off));
            }
            #pragma unroll
            for (int ma = 0; ma < 2; ++ma)
                #pragma unroll
                for (int ng = 0; ng < 4; ++ng)
                    #pragma unroll
                    for (int h = 0; h < 2; ++h) {
                        const int na = ng * 2 + h;
                        mma16816(acc[ma][na], ah[ma], bh[ng][h], bh[ng][2 + h]);
                        mma16816(acc[ma][na], al[ma], bh[ng][h], bh[ng][2 + h]);
                    }
        }
        // no trailing sync: next iteration's barrier protects buffer reuse
    }

    // epilogue: direct stores (float2), optional residual
    const int mrow = lane >> 2;          // 0..7
    const int ncol = (lane & 3) * 2;
    #pragma unroll
    for (int ma = 0; ma < 2; ++ma) {
        #pragma unroll
        for (int na = 0; na < 8; ++na) {
            const int m = m0 + wm0 + ma * 16 + mrow;
            const int n = n0 + wn0 + na * 8 + ncol;
            size_t o0 = (size_t)m * N + n;
            size_t o1 = o0 + (size_t)8 * N;
            float2 v0 = make_float2(acc[ma][na][0], acc[ma][na][1]);
            float2 v1 = make_float2(acc[ma][na][2], acc[ma][na][3]);
            if (R) {
                float2 r0 = *reinterpret_cast<const float2*>(R + o0);
                float2 r1 = *reinterpret_cast<const float2*>(R + o1);
                v0.x += r0.x; v0.y += r0.y;
                v1.x += r1.x; v1.y += r1.y;
            }
            *reinterpret_cast<float2*>(C + o0) = v0;
            *reinterpret_cast<float2*>(C + o1) = v1;
        }
    }
}

// ================= weight transpose + fp16: [K,N]f32 -> [N,K]fp16 =============
__global__ void wsplit_kernel(const float* __restrict__ W,
                              __half* __restrict__ Th,
                              int K, int N)
{
    __shared__ float t[32][33];
    int n0 = blockIdx.x * 32, k0 = blockIdx.y * 32;
    int tx = threadIdx.x & 31, ty = threadIdx.x >> 5;   // 256 thr: ty 0..7
    #pragma unroll
    for (int r = ty; r < 32; r += 8)
        t[r][tx] = W[(size_t)(k0 + r) * N + n0 + tx];
    __syncthreads();
    #pragma unroll
    for (int r = ty; r < 32; r += 8) {
        float v = t[tx][r];                       // W[k0+tx][n0+r]
        Th[(size_t)(n0 + r) * K + k0 + tx] = __float2half_rn(v);
    }
}

// ---------------- RMSNorm + fp16 split ----------------------------------------
__global__ void rmsnorm_split_kernel(const float* __restrict__ x,
                                     const float* __restrict__ w,
                                     __half* __restrict__ oh,
                                     __half* __restrict__ ol) {
    const int D = DMODEL;
    size_t row = blockIdx.x;
    const float4* xr = reinterpret_cast<const float4*>(x + row * D);
    const float4* wr = reinterpret_cast<const float4*>(w);

    int tid = threadIdx.x;
    float4 xv = xr[tid];
    float ss = xv.x*xv.x + xv.y*xv.y + xv.z*xv.z + xv.w*xv.w;
    #pragma unroll
    for (int off = 16; off; off >>= 1)
        ss += __shfl_xor_sync(0xffffffffu, ss, off);
    __shared__ float red[8];
    int lane = tid & 31, warp = tid >> 5;
    if (lane == 0) red[warp] = ss;
    __syncthreads();
    if (tid < 32) {
        float v = (tid < 8) ? red[tid] : 0.0f;
        #pragma unroll
        for (int off = 4; off; off >>= 1)
            v += __shfl_xor_sync(0xffffffffu, v, off);
        if (tid == 0) red[0] = rsqrtf(v * (1.0f / D) + EPS);
    }
    __syncthreads();
    float inv = red[0];
    float4 wv = wr[tid];
    float f[4];
    f[0] = xv.x * inv * wv.x; f[1] = xv.y * inv * wv.y;
    f[2] = xv.z * inv * wv.z; f[3] = xv.w * inv * wv.w;

    alignas(8) __half hv[4], lv[4];
    #pragma unroll
    for (int j = 0; j < 4; ++j) {
        hv[j] = __float2half_rn(f[j]);
        lv[j] = __float2half_rn(f[j] - __half2float(hv[j]));
    }
    size_t b = row * D + tid * 4;
    *reinterpret_cast<uint2*>(oh + b) = *reinterpret_cast<uint2*>(hv);
    *reinterpret_cast<uint2*>(ol + b) = *reinterpret_cast<uint2*>(lv);
}

// ---------------- Tiled windowed causal attention -----------------------------
// 64 queries per block; K/V span (<=127 rows) streamed through smem in chunks.
#define ATQ  64
#define SPAD 129
#define KPAD 68
#define VPAD 132
#define S_FLOATS (64 * SPAD)                       // 8256
#define SCR_FLOATS (128 * VPAD)                    // 16896
#define ATTN_SMEM ((S_FLOATS + SCR_FLOATS) * 4)    // 100608 B

__global__ __launch_bounds__(256, 1)
void attn_tile_kernel(const float* __restrict__ qkv,
                      __half* __restrict__ oh,
                      __half* __restrict__ ol)
{
    extern __shared__ float sm[];
    float* S   = sm;                 // [64][SPAD]
    float* scr = sm + S_FLOATS;
    float* Qc  = scr;                // [64][KPAD]   (phase 1)
    float* Kc  = scr + 64 * KPAD;    // [128][KPAD]  (phase 1)
    float* Vc  = scr;                // [128][VPAD]  (phase 2)

    const int tid  = threadIdx.x;
    const int ty   = tid >> 5;
    const int lane = tid & 31;
    const int blk  = blockIdx.x;
    const int b    = blk >> 5;
    const int t0   = (blk & 31) * ATQ;
    const int jlo  = (t0 == 0) ? 0 : t0 - (WIN - 1);
    const int span = t0 + ATQ - jlo;         // <= 127
    const size_t rowbase = (size_t)b * SEQ;
    const float scale = 0.03125f;

    const int qi0 = ty * 8;
    const int bs  = (t0 == 0) ? 0 : qi0;

    for (int i = tid; i < S_FLOATS; i += 256) S[i] = 0.0f;

    int kkc[3];
    #pragma unroll
    for (int r = 0; r < 3; ++r) {
        int kk = bs + lane + 32 * r;
        kkc[r] = kk < 128 ? kk : 127;
    }

    float acc[8][3];
    #pragma unroll
    for (int q = 0; q < 8; ++q)
        #pragma unroll
        for (int r = 0; r < 3; ++r) acc[q][r] = 0.0f;

    // ---- phase 1: scores over 16 d-chunks of 64 ----
    for (int dc = 0; dc < 16; ++dc) {
        const int d0 = dc * 64;
        {
            int r = tid >> 2, c0 = (tid & 3) * 16;
            const float* src = qkv + (rowbase + t0 + r) * 3072 + d0 + c0;
            float* dst = Qc + r * KPAD + c0;
            #pragma unroll
            for (int s = 0; s < 4; ++s)
                *reinterpret_cast<float4*>(dst + s * 4) =
                    *reinterpret_cast<const float4*>(src + s * 4);
        }
        {
            int r = tid >> 1, c0 = (tid & 1) * 32;
            if (r < span) {
                const float* src = qkv + (rowbase + jlo + r) * 3072 + 1024 + d0 + c0;
                float* dst = Kc + r * KPAD + c0;
                #pragma unroll
                for (int s = 0; s < 8; ++s)
                    *reinterpret_cast<float4*>(dst + s * 4) =
                        *reinterpret_cast<const float4*>(src + s * 4);
            }
        }
        __syncthreads();

        #pragma unroll 4
        for (int d4 = 0; d4 < 64; d4 += 4) {
            float4 kf[3];
            #pragma unroll
            for (int r = 0; r < 3; ++r)
                kf[r] = *reinterpret_cast<const float4*>(Kc + kkc[r] * KPAD + d4);
            #pragma unroll
            for (int q = 0; q < 8; ++q) {
                float4 qf = *reinterpret_cast<const float4*>(Qc + (qi0 + q) * KPAD + d4);
                #pragma unroll
                for (int r = 0; r < 3; ++r) {
                    acc[q][r] = fmaf(qf.x, kf[r].x, acc[q][r]);
                    acc[q][r] = fmaf(qf.y, kf[r].y, acc[q][r]);
                    acc[q][r] = fmaf(qf.z, kf[r].z, acc[q][r]);
                    acc[q][r] = fmaf(qf.w, kf[r].w, acc[q][r]);
                }
            }
        }
        __syncthreads();
    }

    #pragma unroll
    for (int q = 0; q < 8; ++q)
        #pragma unroll
        for (int r = 0; r < 3; ++r) {
            int kk = bs + lane + 32 * r;
            if (kk < 128) S[(qi0 + q) * SPAD + kk] = acc[q][r] * scale;
        }
    __syncthreads();

    // ---- phase 2: softmax (one thread per query) ----
    if (tid < ATQ) {
        const int qi  = tid;
        const int ti  = t0 + qi;
        const int wlo = ((ti >= WIN - 1) ? ti - (WIN - 1) : 0) - jlo;
        const int whi = ti - jlo;
        float* row = S + qi * SPAD;
        float m = -1e30f;
        for (int jj = wlo; jj <= whi; ++jj) m = fmaxf(m, row[jj]);
        float sum = 0.0f;
        for (int jj = wlo; jj <= whi; ++jj) {
            float e = __expf(row[jj] - m);
            row[jj] = e;
            sum += e;
        }
        float inv = 1.0f / sum;
        for (int jj = 0; jj < SPAD; ++jj)
            row[jj] = (jj >= wlo && jj <= whi) ? row[jj] * inv : 0.0f;
    }
    __syncthreads();

    // ---- phase 3: PV over 8 d-chunks of 128 ----
    const int js = (t0 == 0) ? 0 : qi0;
    const int je = (t0 == 0) ? (qi0 + 7) : (qi0 + 70);
    for (int vc = 0; vc < 8; ++vc) {
        const int d0 = vc * 128;
        {
            int r = tid >> 1, c0 = (tid & 1) * 64;
            if (r < span) {
                const float* src = qkv + (rowbase + jlo + r) * 3072 + 2048 + d0 + c0;
                float* dst = Vc + r * VPAD + c0;
                #pragma unroll
                for (int s = 0; s < 16; ++s)
                    *reinterpret_cast<float4*>(dst + s * 4) =
                        *reinterpret_cast<const float4*>(src + s * 4);
            }
        }
        __syncthreads();

        float4 out[8];
        #pragma unroll
        for (int q = 0; q < 8; ++q) out[q] = make_float4(0.f, 0.f, 0.f, 0.f);

        for (int jj = js; jj <= je; ++jj) {
            float4 v = *reinterpret_cast<const float4*>(Vc + jj * VPAD + lane * 4);
            #pragma unroll
            for (int q = 0; q < 8; ++q) {
                float w = S[(qi0 + q) * SPAD + jj];
                out[q].x = fmaf(w, v.x, out[q].x);
                out[q].y = fmaf(w, v.y, out[q].y);
                out[q].z = fmaf(w, v.z, out[q].z);
                out[q].w = fmaf(w, v.w, out[q].w);
            }
        }

        #pragma unroll
        for (int q = 0; q < 8; ++q) {
            size_t o = (rowbase + t0 + qi0 + q) * DMODEL + d0 + lane * 4;
            float f[4] = {out[q].x, out[q].y, out[q].z, out[q].w};
            alignas(8) __half hv[4], lv[4];
            #pragma unroll
            for (int j = 0; j < 4; ++j) {
                hv[j] = __float2half_rn(f[j]);
                lv[j] = __float2half_rn(f[j] - __half2float(hv[j]));
            }
            *reinterpret_cast<uint2*>(oh + o) = *reinterpret_cast<uint2*>(hv);
            *reinterpret_cast<uint2*>(ol + o) = *reinterpret_cast<uint2*>(lv);
        }
        __syncthreads();
    }
}

// ---------------- SwiGLU + fp16 split (fused h13 input) ------------------------
__global__ void swiglu_split_kernel(const float* __restrict__ h13,
                                    __half* __restrict__ gh,
                                    __half* __restrict__ gl, int n4) {
    int idx = blockIdx.x * blockDim.x + threadIdx.x;
    if (idx >= n4) return;
    int row = idx >> 9;
    int cg  = idx & 511;
    const float* base = h13 + (size_t)row * (2 * DFFN) + cg * 4;
    float4 a = *reinterpret_cast<const float4*>(base);
    float4 c = *reinterpret_cast<const float4*>(base + DFFN);
    float f[4];
    f[0] = a.x / (1.0f + __expf(-a.x)) * c.x;
    f[1] = a.y / (1.0f + __expf(-a.y)) * c.y;
    f[2] = a.z / (1.0f + __expf(-a.z)) * c.z;
    f[3] = a.w / (1.0f + __expf(-a.w)) * c.w;
    alignas(8) __half hv[4], lv[4];
    #pragma unroll
    for (int j = 0; j < 4; ++j) {
        hv[j] = __float2half_rn(f[j]);
        lv[j] = __float2half_rn(f[j] - __half2float(hv[j]));
    }
    size_t o = (size_t)row * DFFN + cg * 4;
    *reinterpret_cast<uint2*>(gh + o) = *reinterpret_cast<uint2*>(hv);
    *reinterpret_cast<uint2*>(gl + o) = *reinterpret_cast<uint2*>(lv);
}

// ---------------- launch -------------------------------------------------------
extern "C" void kernel_launch(void* const* d_in, const int* in_sizes, int n_in,
                              void* d_out, int out_size) {
    const float* x       = (const float*)d_in[0];
    const float* norm1_w = (const float*)d_in[1];
    const float* norm2_w = (const float*)d_in[2];
    const float* Wq      = (const float*)d_in[3];
    const float* Wk      = (const float*)d_in[4];
    const float* Wv      = (const float*)d_in[5];
    const float* Wo      = (const float*)d_in[6];
    const float* W1      = (const float*)d_in[7];
    const float* W2      = (const float*)d_in[8];
    const float* W3      = (const float*)d_in[9];
    float* out = (float*)d_out;

    float *p_qkv, *p_xmid, *p_h13;
    cudaGetSymbolAddress((void**)&p_qkv,  g_qkv);
    cudaGetSymbolAddress((void**)&p_xmid, g_xmid);
    cudaGetSymbolAddress((void**)&p_h13,  g_h13);

    __half *xn_h, *xn_l, *att_h, *att_l, *xn2_h, *xn2_l, *gate_h, *gate_l;
    cudaGetSymbolAddress((void**)&xn_h,  g_xn_h);
    cudaGetSymbolAddress((void**)&xn_l,  g_xn_l);
    cudaGetSymbolAddress((void**)&att_h, g_att_h);
    cudaGetSymbolAddress((void**)&att_l, g_att_l);
    cudaGetSymbolAddress((void**)&xn2_h, g_xn2_h);
    cudaGetSymbolAddress((void**)&xn2_l, g_xn2_l);
    cudaGetSymbolAddress((void**)&gate_h, g_gate_h);
    cudaGetSymbolAddress((void**)&gate_l, g_gate_l);

    __half *wqkv, *wo, *w13, *w2;
    cudaGetSymbolAddress((void**)&wqkv, g_wqkv);
    cudaGetSymbolAddress((void**)&wo,   g_wo);
    cudaGetSymbolAddress((void**)&w13,  g_w13);
    cudaGetSymbolAddress((void**)&w2,   g_w2);

    cudaFuncSetAttribute(gemm_fp16x2, cudaFuncAttributeMaxDynamicSharedMemorySize, GEMM_SMEM);
    cudaFuncSetAttribute(attn_tile_kernel, cudaFuncAttributeMaxDynamicSharedMemorySize, ATTN_SMEM);

    const int M = MROWS;                 // 8192
    const int DD = DMODEL * DMODEL;
    dim3 gQKV(3 * DMODEL / GBN, M / GBM);   // (24, 64)
    dim3 gD  (DMODEL / GBN,     M / GBM);   // (8, 64)
    dim3 gF13(2 * DFFN / GBN,   M / GBM);   // (32, 64)

    // weight transpose -> fp16 [N,K]
    wsplit_kernel<<<dim3(DMODEL/32, DMODEL/32), 256>>>(Wq, wqkv,          DMODEL, DMODEL);
    wsplit_kernel<<<dim3(DMODEL/32, DMODEL/32), 256>>>(Wk, wqkv + DD,     DMODEL, DMODEL);
    wsplit_kernel<<<dim3(DMODEL/32, DMODEL/32), 256>>>(Wv, wqkv + 2*DD,   DMODEL, DMODEL);
    wsplit_kernel<<<dim3(DMODEL/32, DMODEL/32), 256>>>(Wo, wo,            DMODEL, DMODEL);
    wsplit_kernel<<<dim3(DFFN/32,   DMODEL/32), 256>>>(W1, w13,           DMODEL, DFFN);
    wsplit_kernel<<<dim3(DFFN/32,   DMODEL/32), 256>>>(W3, w13 + DFFN*DMODEL, DMODEL, DFFN);
    wsplit_kernel<<<dim3(DMODEL/32, DFFN/32),   256>>>(W2, w2,            DFFN, DMODEL);

    // 1. norm1 (+ split)
    rmsnorm_split_kernel<<<M, 256>>>(x, norm1_w, xn_h, xn_l);
    // 2. fused QKV projection -> [M, 3072]
    gemm_fp16x2<<<gQKV, 256, GEMM_SMEM>>>(xn_h, xn_l, wqkv, nullptr, p_qkv, 3*DMODEL, DMODEL);
    // 3. tiled windowed attention (+ split)
    attn_tile_kernel<<<M / ATQ, 256, ATTN_SMEM>>>(p_qkv, att_h, att_l);
    // 4. x_mid = x + attended @ Wo
    gemm_fp16x2<<<gD, 256, GEMM_SMEM>>>(att_h, att_l, wo, x, p_xmid, DMODEL, DMODEL);
    // 5. norm2 (+ split)
    rmsnorm_split_kernel<<<M, 256>>>(p_xmid, norm2_w, xn2_h, xn2_l);
    // 6. fused FFN up projection -> [M, 4096]
    gemm_fp16x2<<<gF13, 256, GEMM_SMEM>>>(xn2_h, xn2_l, w13, nullptr, p_h13, 2*DFFN, DMODEL);
    // 7. gate = silu(h1) * h3 (+ split)
    {
        int n4 = M * DFFN / 4;
        swiglu_split_kernel<<<(n4 + 255) / 256, 256>>>(p_h13, gate_h, gate_l, n4);
    }
    // 8. out = x_mid + gate @ W2
    gemm_fp16x2<<<gD, 256, GEMM_SMEM>>>(gate_h, gate_l, w2, p_xmid, out, DMODEL, DFFN);
}

// round 6
// speedup vs baseline: 2.6389x; 1.0138x over previous
#include <cuda_runtime.h>
#include <cuda_fp16.h>
#include <cstdint>
#include <math.h>

// Problem constants
#define BATCH 4
#define SEQ   2048
#define DMODEL 1024
#define DFFN  2048
#define WIN   64
#define MROWS (BATCH*SEQ)   // 8192
#define EPS   1e-6f

// ---------------- scratch (device globals; no allocation allowed) -------------
__device__ float g_qkv [MROWS * 3 * DMODEL];   // fused [M, 3072]: q|k|v
__device__ float g_xmid[MROWS * DMODEL];
// fp16 split activations (A operands, [M,K])
__device__ __half g_xn_h [MROWS * DMODEL];
__device__ __half g_xn_l [MROWS * DMODEL];
__device__ __half g_att_h[MROWS * DMODEL];
__device__ __half g_att_l[MROWS * DMODEL];
__device__ __half g_xn2_h[MROWS * DMODEL];
__device__ __half g_xn2_l[MROWS * DMODEL];
__device__ __half g_gate_h[MROWS * DFFN];
__device__ __half g_gate_l[MROWS * DFFN];
// fp16 transposed weights [N,K]; QKV fused along N; W1/W3 interleaved by 8 cols
__device__ __half g_wqkv[3 * DMODEL * DMODEL];
__device__ __half g_wo  [DMODEL * DMODEL];
__device__ __half g_w13i[2 * DFFN * DMODEL];
__device__ __half g_w2  [DMODEL * DFFN];

// ============================= PTX helpers ====================================
__device__ __forceinline__ uint32_t smem_u32(const void* p) {
    uint32_t a;
    asm("{ .reg .u64 t; cvta.to.shared.u64 t, %1; cvt.u32.u64 %0, t; }"
        : "=r"(a) : "l"(p));
    return a;
}
__device__ __forceinline__ uint32_t swz128(uint32_t o) {
    return o ^ ((o >> 3) & 0x70);
}
__device__ __forceinline__ void cpasync16(uint32_t dst, const void* src) {
    asm volatile("cp.async.cg.shared.global [%0], [%1], 16;"
                 :: "r"(dst), "l"(__cvta_generic_to_global(src)) : "memory");
}
__device__ __forceinline__ void cp_commit() {
    asm volatile("cp.async.commit_group;" ::: "memory");
}
template <int N>
__device__ __forceinline__ void cp_wait() {
    asm volatile("cp.async.wait_group %0;" :: "n"(N) : "memory");
}
__device__ __forceinline__ void ldsm_x4(uint32_t* r, uint32_t addr) {
    asm volatile("ldmatrix.sync.aligned.m8n8.x4.shared.b16 {%0,%1,%2,%3}, [%4];"
                 : "=r"(r[0]), "=r"(r[1]), "=r"(r[2]), "=r"(r[3]) : "r"(addr));
}
__device__ __forceinline__ void mma16816(float* c, const uint32_t* a,
                                         uint32_t b0, uint32_t b1) {
    asm volatile(
        "mma.sync.aligned.m16n8k16.row.col.f32.f16.f16.f32 "
        "{%0,%1,%2,%3}, {%4,%5,%6,%7}, {%8,%9}, {%0,%1,%2,%3};"
        : "+f"(c[0]), "+f"(c[1]), "+f"(c[2]), "+f"(c[3])
        : "r"(a[0]), "r"(a[1]), "r"(a[2]), "r"(a[3]), "r"(b0), "r"(b1));
}

// ====================== fp16x2 GEMM via mma.sync ==============================
// C[M,N] = (Ah+Al)[M,K] @ Bh[N,K]^T (+R), fp32 out.
// Tile 128x128, BK=64, 256 threads (8 warps, 4x2), 4-stage cp.async pipeline.
#define GBM 128
#define GBN 128
#define GBK 64
#define NSTAGE 4
#define AH_OFF 0
#define AL_OFF 16384
#define BH_OFF 32768
#define STAGE_BYTES 49152
#define GEMM_SMEM (NSTAGE * STAGE_BYTES)   // 196608

__device__ __forceinline__ void gemm_load_stage(
    uint32_t sb,
    const __half* __restrict__ Ah, const __half* __restrict__ Al,
    const __half* __restrict__ Bh,
    int m0, int n0, int k0, int K, int tid)
{
    const int row  = tid >> 1;            // 0..127
    const int half = (tid & 1) * 64;      // byte offset within 128B row
    const uint32_t so = row * 128 + half;

    const char* pAh = (const char*)(Ah + (size_t)(m0 + row) * K + k0) + half;
    const char* pAl = (const char*)(Al + (size_t)(m0 + row) * K + k0) + half;
    const char* pBh = (const char*)(Bh + (size_t)(n0 + row) * K + k0) + half;

    #pragma unroll
    for (int s = 0; s < 4; ++s) {
        uint32_t d = swz128(so + s * 16);
        cpasync16(sb + AH_OFF + d, pAh + s * 16);
        cpasync16(sb + AL_OFF + d, pAl + s * 16);
        cpasync16(sb + BH_OFF + d, pBh + s * 16);
    }
}

// Shared mainloop: accumulates the 128x128 tile into acc.
__device__ __forceinline__ void gemm_mainloop(
    float (&acc)[2][8][4],
    const __half* __restrict__ Ah, const __half* __restrict__ Al,
    const __half* __restrict__ Bh,
    int m0, int n0, int K, int tid, int wid, int lane, uint32_t base)
{
    const int wm0 = (wid & 3) * 32;
    const int wn0 = (wid >> 2) * 64;
    const int nk = K / GBK;

    #pragma unroll
    for (int i = 0; i < 2; ++i)
        #pragma unroll
        for (int j = 0; j < 8; ++j)
            #pragma unroll
            for (int t = 0; t < 4; ++t) acc[i][j][t] = 0.0f;

    #pragma unroll
    for (int p = 0; p < NSTAGE - 1; ++p) {
        gemm_load_stage(base + p * STAGE_BYTES, Ah, Al, Bh, m0, n0, p * GBK, K, tid);
        cp_commit();
    }

    const uint32_t lrow  = (lane & 15);
    const uint32_t lkoff = (lane >> 4) << 4;

    for (int i = 0; i < nk; ++i) {
        cp_wait<NSTAGE - 2>();
        __syncthreads();

        const int nc = i + NSTAGE - 1;
        if (nc < nk)
            gemm_load_stage(base + (nc % NSTAGE) * STAGE_BYTES,
                            Ah, Al, Bh, m0, n0, nc * GBK, K, tid);
        cp_commit();

        const uint32_t sb = base + (i % NSTAGE) * STAGE_BYTES;
        #pragma unroll
        for (int ks = 0; ks < 4; ++ks) {
            uint32_t ah[2][4], al[2][4], bh[4][4];
            #pragma unroll
            for (int ma = 0; ma < 2; ++ma) {
                uint32_t off = (wm0 + ma * 16 + lrow) * 128 + ks * 32 + lkoff;
                uint32_t ad = sb + swz128(off);
                ldsm_x4(ah[ma], ad + AH_OFF);
                ldsm_x4(al[ma], ad + AL_OFF);
            }
            #pragma unroll
            for (int ng = 0; ng < 4; ++ng) {
                uint32_t off = (wn0 + ng * 16 + lrow) * 128 + ks * 32 + lkoff;
                ldsm_x4(bh[ng], sb + BH_OFF + swz128(off));
            }
            #pragma unroll
            for (int ma = 0; ma < 2; ++ma)
                #pragma unroll
                for (int ng = 0; ng < 4; ++ng)
                    #pragma unroll
                    for (int h = 0; h < 2; ++h) {
                        const int na = ng * 2 + h;
                        mma16816(acc[ma][na], ah[ma], bh[ng][h], bh[ng][2 + h]);
                        mma16816(acc[ma][na], al[ma], bh[ng][h], bh[ng][2 + h]);
                    }
        }
    }
}

__global__ __launch_bounds__(256, 1)
void gemm_fp16x2(const __half* __restrict__ Ah, const __half* __restrict__ Al,
                 const __half* __restrict__ Bh,
                 const float* __restrict__ R, float* __restrict__ C,
                 int N, int K)
{
    extern __shared__ char smem[];
    const int tid  = threadIdx.x;
    const int wid  = tid >> 5;
    const int lane = tid & 31;
    const int m0 = blockIdx.y * GBM;
    const int n0 = blockIdx.x * GBN;
    const uint32_t base = smem_u32(smem);

    float acc[2][8][4];
    gemm_mainloop(acc, Ah, Al, Bh, m0, n0, K, tid, wid, lane, base);

    const int wm0 = (wid & 3) * 32;
    const int wn0 = (wid >> 2) * 64;
    const int mrow = lane >> 2;
    const int ncol = (lane & 3) * 2;
    #pragma unroll
    for (int ma = 0; ma < 2; ++ma) {
        #pragma unroll
        for (int na = 0; na < 8; ++na) {
            const int m = m0 + wm0 + ma * 16 + mrow;
            const int n = n0 + wn0 + na * 8 + ncol;
            size_t o0 = (size_t)m * N + n;
            size_t o1 = o0 + (size_t)8 * N;
            float2 v0 = make_float2(acc[ma][na][0], acc[ma][na][1]);
            float2 v1 = make_float2(acc[ma][na][2], acc[ma][na][3]);
            if (R) {
                float2 r0 = *reinterpret_cast<const float2*>(R + o0);
                float2 r1 = *reinterpret_cast<const float2*>(R + o1);
                v0.x += r0.x; v0.y += r0.y;
                v1.x += r1.x; v1.y += r1.y;
            }
            *reinterpret_cast<float2*>(C + o0) = v0;
            *reinterpret_cast<float2*>(C + o1) = v1;
        }
    }
}

// W13 GEMM with fused SwiGLU epilogue. B = interleaved W1|W3 (phys N = 4096):
// phys rows [16t..16t+8) = W1 cols [8t..8t+8), [16t+8..16t+16) = W3 same cols.
// Writes gate (fp16 h/l) [M, DFFN].
__global__ __launch_bounds__(256, 1)
void gemm_fp16x2_swiglu(const __half* __restrict__ Ah, const __half* __restrict__ Al,
                        const __half* __restrict__ Bh,
                        __half* __restrict__ gh, __half* __restrict__ gl,
                        int K)
{
    extern __shared__ char smem[];
    const int tid  = threadIdx.x;
    const int wid  = tid >> 5;
    const int lane = tid & 31;
    const int m0 = blockIdx.y * GBM;
    const int n0 = blockIdx.x * GBN;
    const uint32_t base = smem_u32(smem);

    float acc[2][8][4];
    gemm_mainloop(acc, Ah, Al, Bh, m0, n0, K, tid, wid, lane, base);

    const int wm0 = (wid & 3) * 32;
    const int wn0 = (wid >> 2) * 64;
    const int mrow = lane >> 2;
    const int ncol = (lane & 3) * 2;
    const int gbase = ((n0 + wn0) >> 1);
    #pragma unroll
    for (int ma = 0; ma < 2; ++ma) {
        #pragma unroll
        for (int g = 0; g < 4; ++g) {
            const float* a1 = acc[ma][2 * g];       // W1 (silu input)
            const float* a3 = acc[ma][2 * g + 1];   // W3
            const int gcol = gbase + g * 8 + ncol;
            #pragma unroll
            for (int hf = 0; hf < 2; ++hf) {
                const int m = m0 + wm0 + ma * 16 + mrow + hf * 8;
                float x0 = a1[hf * 2 + 0], x1 = a1[hf * 2 + 1];
                float f0 = x0 / (1.0f + __expf(-x0)) * a3[hf * 2 + 0];
                float f1 = x1 / (1.0f + __expf(-x1)) * a3[hf * 2 + 1];
                __half h0 = __float2half_rn(f0);
                __half h1 = __float2half_rn(f1);
                __half l0 = __float2half_rn(f0 - __half2float(h0));
                __half l1 = __float2half_rn(f1 - __half2float(h1));
                size_t o = (size_t)m * DFFN + gcol;
                __half2 hv; hv.x = h0; hv.y = h1;
                __half2 lv; lv.x = l0; lv.y = l1;
                *reinterpret_cast<__half2*>(gh + o) = hv;
                *reinterpret_cast<__half2*>(gl + o) = lv;
            }
        }
    }
}

// ============ merged weight transpose: [K,N]f32 -> [N,K]fp16, one launch ======
// mode 0: dst row = n. mode 1: dst row = 16*(n>>3)+(n&7)   (W1 interleave)
//                      mode 2: dst row = 16*(n>>3)+(n&7)+8 (W3 interleave)
#define NWJOBS 7
struct WJobs {
    const float* src[NWJOBS];
    __half* dst[NWJOBS];
    int K[NWJOBS];
    int N[NWJOBS];
    int mode[NWJOBS];
    int tile_off[NWJOBS + 1];
};

__global__ void wsplit_all_kernel(WJobs jobs)
{
    __shared__ float t[32][33];
    int tile = blockIdx.x;
    int j = 0;
    #pragma unroll
    for (int i = 0; i < NWJOBS; ++i)
        if (tile >= jobs.tile_off[i + 1]) j = i + 1;
    const int lt   = tile - jobs.tile_off[j];
    const int K    = jobs.K[j];
    const int N    = jobs.N[j];
    const int mode = jobs.mode[j];
    const float* W = jobs.src[j];
    __half* Th     = jobs.dst[j];
    const int ntx  = N >> 5;
    const int n0 = (lt % ntx) * 32;
    const int k0 = (lt / ntx) * 32;

    int tx = threadIdx.x & 31, ty = threadIdx.x >> 5;
    #pragma unroll
    for (int r = ty; r < 32; r += 8)
        t[r][tx] = W[(size_t)(k0 + r) * N + n0 + tx];
    __syncthreads();
    #pragma unroll
    for (int r = ty; r < 32; r += 8) {
        float v = t[tx][r];                       // W[k0+tx][n0+r]
        int n = n0 + r;
        int p = (mode == 0) ? n : (16 * (n >> 3) + (n & 7) + ((mode == 2) ? 8 : 0));
        Th[(size_t)p * K + k0 + tx] = __float2half_rn(v);
    }
}

// ---------------- RMSNorm + fp16 split ----------------------------------------
__global__ void rmsnorm_split_kernel(const float* __restrict__ x,
                                     const float* __restrict__ w,
                                     __half* __restrict__ oh,
                                     __half* __restrict__ ol) {
    const int D = DMODEL;
    size_t row = blockIdx.x;
    const float4* xr = reinterpret_cast<const float4*>(x + row * D);
    const float4* wr = reinterpret_cast<const float4*>(w);

    int tid = threadIdx.x;
    float4 xv = xr[tid];
    float ss = xv.x*xv.x + xv.y*xv.y + xv.z*xv.z + xv.w*xv.w;
    #pragma unroll
    for (int off = 16; off; off >>= 1)
        ss += __shfl_xor_sync(0xffffffffu, ss, off);
    __shared__ float red[8];
    int lane = tid & 31, warp = tid >> 5;
    if (lane == 0) red[warp] = ss;
    __syncthreads();
    if (tid < 32) {
        float v = (tid < 8) ? red[tid] : 0.0f;
        #pragma unroll
        for (int off = 4; off; off >>= 1)
            v += __shfl_xor_sync(0xffffffffu, v, off);
        if (tid == 0) red[0] = rsqrtf(v * (1.0f / D) + EPS);
    }
    __syncthreads();
    float inv = red[0];
    float4 wv = wr[tid];
    float f[4];
    f[0] = xv.x * inv * wv.x; f[1] = xv.y * inv * wv.y;
    f[2] = xv.z * inv * wv.z; f[3] = xv.w * inv * wv.w;

    alignas(8) __half hv[4], lv[4];
    #pragma unroll
    for (int j = 0; j < 4; ++j) {
        hv[j] = __float2half_rn(f[j]);
        lv[j] = __float2half_rn(f[j] - __half2float(hv[j]));
    }
    size_t b = row * D + tid * 4;
    *reinterpret_cast<uint2*>(oh + b) = *reinterpret_cast<uint2*>(hv);
    *reinterpret_cast<uint2*>(ol + b) = *reinterpret_cast<uint2*>(lv);
}

// ---------------- Tiled windowed causal attention -----------------------------
#define ATQ  64
#define SPAD 129
#define KPAD 68
#define VPAD 132
#define S_FLOATS (64 * SPAD)
#define SCR_FLOATS (128 * VPAD)
#define ATTN_SMEM ((S_FLOATS + SCR_FLOATS) * 4)    // 100608 B

__global__ __launch_bounds__(256, 1)
void attn_tile_kernel(const float* __restrict__ qkv,
                      __half* __restrict__ oh,
                      __half* __restrict__ ol)
{
    extern __shared__ float sm[];
    float* S   = sm;
    float* scr = sm + S_FLOATS;
    float* Qc  = scr;
    float* Kc  = scr + 64 * KPAD;
    float* Vc  = scr;

    const int tid  = threadIdx.x;
    const int ty   = tid >> 5;
    const int lane = tid & 31;
    const int blk  = blockIdx.x;
    const int b    = blk >> 5;
    const int t0   = (blk & 31) * ATQ;
    const int jlo  = (t0 == 0) ? 0 : t0 - (WIN - 1);
    const int span = t0 + ATQ - jlo;
    const size_t rowbase = (size_t)b * SEQ;
    const float scale = 0.03125f;

    const int qi0 = ty * 8;
    const int bs  = (t0 == 0) ? 0 : qi0;

    for (int i = tid; i < S_FLOATS; i += 256) S[i] = 0.0f;

    int kkc[3];
    #pragma unroll
    for (int r = 0; r < 3; ++r) {
        int kk = bs + lane + 32 * r;
        kkc[r] = kk < 128 ? kk : 127;
    }

    float acc[8][3];
    #pragma unroll
    for (int q = 0; q < 8; ++q)
        #pragma unroll
        for (int r = 0; r < 3; ++r) acc[q][r] = 0.0f;

    for (int dc = 0; dc < 16; ++dc) {
        const int d0 = dc * 64;
        {
            int r = tid >> 2, c0 = (tid & 3) * 16;
            const float* src = qkv + (rowbase + t0 + r) * 3072 + d0 + c0;
            float* dst = Qc + r * KPAD + c0;
            #pragma unroll
            for (int s = 0; s < 4; ++s)
                *reinterpret_cast<float4*>(dst + s * 4) =
                    *reinterpret_cast<const float4*>(src + s * 4);
        }
        {
            int r = tid >> 1, c0 = (tid & 1) * 32;
            if (r < span) {
                const float* src = qkv + (rowbase + jlo + r) * 3072 + 1024 + d0 + c0;
                float* dst = Kc + r * KPAD + c0;
                #pragma unroll
                for (int s = 0; s < 8; ++s)
                    *reinterpret_cast<float4*>(dst + s * 4) =
                        *reinterpret_cast<const float4*>(src + s * 4);
            }
        }
        __syncthreads();

        #pragma unroll 4
        for (int d4 = 0; d4 < 64; d4 += 4) {
            float4 kf[3];
            #pragma unroll
            for (int r = 0; r < 3; ++r)
                kf[r] = *reinterpret_cast<const float4*>(Kc + kkc[r] * KPAD + d4);
            #pragma unroll
            for (int q = 0; q < 8; ++q) {
                float4 qf = *reinterpret_cast<const float4*>(Qc + (qi0 + q) * KPAD + d4);
                #pragma unroll
                for (int r = 0; r < 3; ++r) {
                    acc[q][r] = fmaf(qf.x, kf[r].x, acc[q][r]);
                    acc[q][r] = fmaf(qf.y, kf[r].y, acc[q][r]);
                    acc[q][r] = fmaf(qf.z, kf[r].z, acc[q][r]);
                    acc[q][r] = fmaf(qf.w, kf[r].w, acc[q][r]);
                }
            }
        }
        __syncthreads();
    }

    #pragma unroll
    for (int q = 0; q < 8; ++q)
        #pragma unroll
        for (int r = 0; r < 3; ++r) {
            int kk = bs + lane + 32 * r;
            if (kk < 128) S[(qi0 + q) * SPAD + kk] = acc[q][r] * scale;
        }
    __syncthreads();

    if (tid < ATQ) {
        const int qi  = tid;
        const int ti  = t0 + qi;
        const int wlo = ((ti >= WIN - 1) ? ti - (WIN - 1) : 0) - jlo;
        const int whi = ti - jlo;
        float* row = S + qi * SPAD;
        float m = -1e30f;
        for (int jj = wlo; jj <= whi; ++jj) m = fmaxf(m, row[jj]);
        float sum = 0.0f;
        for (int jj = wlo; jj <= whi; ++jj) {
            float e = __expf(row[jj] - m);
            row[jj] = e;
            sum += e;
        }
        float inv = 1.0f / sum;
        for (int jj = 0; jj < SPAD; ++jj)
            row[jj] = (jj >= wlo && jj <= whi) ? row[jj] * inv : 0.0f;
    }
    __syncthreads();

    const int js = (t0 == 0) ? 0 : qi0;
    const int je = (t0 == 0) ? (qi0 + 7) : (qi0 + 70);
    for (int vc = 0; vc < 8; ++vc) {
        const int d0 = vc * 128;
        {
            int r = tid >> 1, c0 = (tid & 1) * 64;
            if (r < span) {
                const float* src = qkv + (rowbase + jlo + r) * 3072 + 2048 + d0 + c0;
                float* dst = Vc + r * VPAD + c0;
                #pragma unroll
                for (int s = 0; s < 16; ++s)
                    *reinterpret_cast<float4*>(dst + s * 4) =
                        *reinterpret_cast<const float4*>(src + s * 4);
            }
        }
        __syncthreads();

        float4 out[8];
        #pragma unroll
        for (int q = 0; q < 8; ++q) out[q] = make_float4(0.f, 0.f, 0.f, 0.f);

        for (int jj = js; jj <= je; ++jj) {
            float4 v = *reinterpret_cast<const float4*>(Vc + jj * VPAD + lane * 4);
            #pragma unroll
            for (int q = 0; q < 8; ++q) {
                float w = S[(qi0 + q) * SPAD + jj];
                out[q].x = fmaf(w, v.x, out[q].x);
                out[q].y = fmaf(w, v.y, out[q].y);
                out[q].z = fmaf(w, v.z, out[q].z);
                out[q].w = fmaf(w, v.w, out[q].w);
            }
        }

        #pragma unroll
        for (int q = 0; q < 8; ++q) {
            size_t o = (rowbase + t0 + qi0 + q) * DMODEL + d0 + lane * 4;
            float f[4] = {out[q].x, out[q].y, out[q].z, out[q].w};
            alignas(8) __half hv[4], lv[4];
            #pragma unroll
            for (int j = 0; j < 4; ++j) {
                hv[j] = __float2half_rn(f[j]);
                lv[j] = __float2half_rn(f[j] - __half2float(hv[j]));
            }
            *reinterpret_cast<uint2*>(oh + o) = *reinterpret_cast<uint2*>(hv);
            *reinterpret_cast<uint2*>(ol + o) = *reinterpret_cast<uint2*>(lv);
        }
        __syncthreads();
    }
}

// ---------------- launch -------------------------------------------------------
extern "C" void kernel_launch(void* const* d_in, const int* in_sizes, int n_in,
                              void* d_out, int out_size) {
    const float* x       = (const float*)d_in[0];
    const float* norm1_w = (const float*)d_in[1];
    const float* norm2_w = (const float*)d_in[2];
    const float* Wq      = (const float*)d_in[3];
    const float* Wk      = (const float*)d_in[4];
    const float* Wv      = (const float*)d_in[5];
    const float* Wo      = (const float*)d_in[6];
    const float* W1      = (const float*)d_in[7];
    const float* W2      = (const float*)d_in[8];
    const float* W3      = (const float*)d_in[9];
    float* out = (float*)d_out;

    float *p_qkv, *p_xmid;
    cudaGetSymbolAddress((void**)&p_qkv,  g_qkv);
    cudaGetSymbolAddress((void**)&p_xmid, g_xmid);

    __half *xn_h, *xn_l, *att_h, *att_l, *xn2_h, *xn2_l, *gate_h, *gate_l;
    cudaGetSymbolAddress((void**)&xn_h,  g_xn_h);
    cudaGetSymbolAddress((void**)&xn_l,  g_xn_l);
    cudaGetSymbolAddress((void**)&att_h, g_att_h);
    cudaGetSymbolAddress((void**)&att_l, g_att_l);
    cudaGetSymbolAddress((void**)&xn2_h, g_xn2_h);
    cudaGetSymbolAddress((void**)&xn2_l, g_xn2_l);
    cudaGetSymbolAddress((void**)&gate_h, g_gate_h);
    cudaGetSymbolAddress((void**)&gate_l, g_gate_l);

    __half *wqkv, *wo, *w13i, *w2;
    cudaGetSymbolAddress((void**)&wqkv, g_wqkv);
    cudaGetSymbolAddress((void**)&wo,   g_wo);
    cudaGetSymbolAddress((void**)&w13i, g_w13i);
    cudaGetSymbolAddress((void**)&w2,   g_w2);

    cudaFuncSetAttribute(gemm_fp16x2, cudaFuncAttributeMaxDynamicSharedMemorySize, GEMM_SMEM);
    cudaFuncSetAttribute(gemm_fp16x2_swiglu, cudaFuncAttributeMaxDynamicSharedMemorySize, GEMM_SMEM);
    cudaFuncSetAttribute(attn_tile_kernel, cudaFuncAttributeMaxDynamicSharedMemorySize, ATTN_SMEM);

    const int M = MROWS;                 // 8192
    const int DD = DMODEL * DMODEL;
    dim3 gQKV(3 * DMODEL / GBN, M / GBM);   // (24, 64)
    dim3 gD  (DMODEL / GBN,     M / GBM);   // (8, 64)
    dim3 gF13(2 * DFFN / GBN,   M / GBM);   // (32, 64)

    // merged weight transpose (7 jobs, one launch)
    {
        WJobs jb;
        const float* srcs[NWJOBS] = {Wq, Wk, Wv, Wo, W1, W3, W2};
        __half* dsts[NWJOBS] = {wqkv, wqkv + DD, wqkv + 2*DD, wo, w13i, w13i, w2};
        int Ks[NWJOBS]    = {DMODEL, DMODEL, DMODEL, DMODEL, DMODEL, DMODEL, DFFN};
        int Ns[NWJOBS]    = {DMODEL, DMODEL, DMODEL, DMODEL, DFFN,   DFFN,   DMODEL};
        int modes[NWJOBS] = {0, 0, 0, 0, 1, 2, 0};
        int off = 0;
        for (int i = 0; i < NWJOBS; ++i) {
            jb.src[i] = srcs[i]; jb.dst[i] = dsts[i];
            jb.K[i] = Ks[i]; jb.N[i] = Ns[i]; jb.mode[i] = modes[i];
            jb.tile_off[i] = off;
            off += (Ns[i] >> 5) * (Ks[i] >> 5);
        }
        jb.tile_off[NWJOBS] = off;
        wsplit_all_kernel<<<off, 256>>>(jb);
    }

    // 1. norm1 (+ split)
    rmsnorm_split_kernel<<<M, 256>>>(x, norm1_w, xn_h, xn_l);
    // 2. fused QKV projection -> [M, 3072]
    gemm_fp16x2<<<gQKV, 256, GEMM_SMEM>>>(xn_h, xn_l, wqkv, nullptr, p_qkv, 3*DMODEL, DMODEL);
    // 3. tiled windowed attention (+ split)
    attn_tile_kernel<<<M / ATQ, 256, ATTN_SMEM>>>(p_qkv, att_h, att_l);
    // 4. x_mid = x + attended @ Wo
    gemm_fp16x2<<<gD, 256, GEMM_SMEM>>>(att_h, att_l, wo, x, p_xmid, DMODEL, DMODEL);
    // 5. norm2 (+ split)
    rmsnorm_split_kernel<<<M, 256>>>(p_xmid, norm2_w, xn2_h, xn2_l);
    // 6. fused FFN up projection + SwiGLU -> gate fp16 h/l [M, 2048]
    gemm_fp16x2_swiglu<<<gF13, 256, GEMM_SMEM>>>(xn2_h, xn2_l, w13i, gate_h, gate_l, DMODEL);
    // 7. out = x_mid + gate @ W2
    gemm_fp16x2<<<gD, 256, GEMM_SMEM>>>(gate_h, gate_l, w2, p_xmid, out, DMODEL, DFFN);
}

// round 7
// speedup vs baseline: 2.6487x; 1.0037x over previous
#include <cuda_runtime.h>
#include <cuda_fp16.h>
#include <cstdint>
#include <math.h>

// Problem constants
#define BATCH 4
#define SEQ   2048
#define DMODEL 1024
#define DFFN  2048
#define WIN   64
#define MROWS (BATCH*SEQ)   // 8192
#define EPS   1e-6f

// ---------------- scratch (device globals; no allocation allowed) -------------
__device__ float g_qkv [MROWS * 3 * DMODEL];   // fused [M, 3072]: q|k|v
__device__ float g_xmid[MROWS * DMODEL];
// fp16 split activations (A operands, [M,K])
__device__ __half g_xn_h [MROWS * DMODEL];
__device__ __half g_xn_l [MROWS * DMODEL];
__device__ __half g_att_h[MROWS * DMODEL];
__device__ __half g_att_l[MROWS * DMODEL];
__device__ __half g_xn2_h[MROWS * DMODEL];
__device__ __half g_xn2_l[MROWS * DMODEL];
__device__ __half g_gate_h[MROWS * DFFN];
__device__ __half g_gate_l[MROWS * DFFN];
// fp16 transposed weights [N,K]; QKV fused along N; W1/W3 interleaved by 8 cols
__device__ __half g_wqkv[3 * DMODEL * DMODEL];
__device__ __half g_wo  [DMODEL * DMODEL];
__device__ __half g_w13i[2 * DFFN * DMODEL];
__device__ __half g_w2  [DMODEL * DFFN];

// ============================= PTX helpers ====================================
__device__ __forceinline__ uint32_t smem_u32(const void* p) {
    uint32_t a;
    asm("{ .reg .u64 t; cvta.to.shared.u64 t, %1; cvt.u32.u64 %0, t; }"
        : "=r"(a) : "l"(p));
    return a;
}
__device__ __forceinline__ uint32_t swz128(uint32_t o) {
    return o ^ ((o >> 3) & 0x70);
}
__device__ __forceinline__ void cpasync16(uint32_t dst, const void* src) {
    asm volatile("cp.async.cg.shared.global [%0], [%1], 16;"
                 :: "r"(dst), "l"(__cvta_generic_to_global(src)) : "memory");
}
__device__ __forceinline__ void cp_commit() {
    asm volatile("cp.async.commit_group;" ::: "memory");
}
template <int N>
__device__ __forceinline__ void cp_wait() {
    asm volatile("cp.async.wait_group %0;" :: "n"(N) : "memory");
}
__device__ __forceinline__ void ldsm_x4(uint32_t* r, uint32_t addr) {
    asm volatile("ldmatrix.sync.aligned.m8n8.x4.shared.b16 {%0,%1,%2,%3}, [%4];"
                 : "=r"(r[0]), "=r"(r[1]), "=r"(r[2]), "=r"(r[3]) : "r"(addr));
}
__device__ __forceinline__ void mma16816(float* c, const uint32_t* a,
                                         uint32_t b0, uint32_t b1) {
    asm volatile(
        "mma.sync.aligned.m16n8k16.row.col.f32.f16.f16.f32 "
        "{%0,%1,%2,%3}, {%4,%5,%6,%7}, {%8,%9}, {%0,%1,%2,%3};"
        : "+f"(c[0]), "+f"(c[1]), "+f"(c[2]), "+f"(c[3])
        : "r"(a[0]), "r"(a[1]), "r"(a[2]), "r"(a[3]), "r"(b0), "r"(b1));
}

// ====================== fp16x2 GEMM via mma.sync ==============================
// C[M,N] = (Ah+Al)[M,K] @ Bh[N,K]^T (+R), fp32 out.
// Tile 128x128, BK=64, 256 threads (8 warps, 4x2), 4-stage cp.async pipeline.
#define GBM 128
#define GBN 128
#define GBK 64
#define NSTAGE 4
#define AH_OFF 0
#define AL_OFF 16384
#define BH_OFF 32768
#define STAGE_BYTES 49152
#define GEMM_SMEM (NSTAGE * STAGE_BYTES)   // 196608

__device__ __forceinline__ void gemm_load_stage(
    uint32_t sb,
    const __half* __restrict__ Ah, const __half* __restrict__ Al,
    const __half* __restrict__ Bh,
    int m0, int n0, int k0, int K, int tid)
{
    const int row  = tid >> 1;            // 0..127
    const int half = (tid & 1) * 64;      // byte offset within 128B row
    const uint32_t so = row * 128 + half;

    const char* pAh = (const char*)(Ah + (size_t)(m0 + row) * K + k0) + half;
    const char* pAl = (const char*)(Al + (size_t)(m0 + row) * K + k0) + half;
    const char* pBh = (const char*)(Bh + (size_t)(n0 + row) * K + k0) + half;

    #pragma unroll
    for (int s = 0; s < 4; ++s) {
        uint32_t d = swz128(so + s * 16);
        cpasync16(sb + AH_OFF + d, pAh + s * 16);
        cpasync16(sb + AL_OFF + d, pAl + s * 16);
        cpasync16(sb + BH_OFF + d, pBh + s * 16);
    }
}

// Shared mainloop: accumulates the 128x128 tile into acc.
__device__ __forceinline__ void gemm_mainloop(
    float (&acc)[2][8][4],
    const __half* __restrict__ Ah, const __half* __restrict__ Al,
    const __half* __restrict__ Bh,
    int m0, int n0, int K, int tid, int wid, int lane, uint32_t base)
{
    const int wm0 = (wid & 3) * 32;
    const int wn0 = (wid >> 2) * 64;
    const int nk = K / GBK;

    #pragma unroll
    for (int i = 0; i < 2; ++i)
        #pragma unroll
        for (int j = 0; j < 8; ++j)
            #pragma unroll
            for (int t = 0; t < 4; ++t) acc[i][j][t] = 0.0f;

    #pragma unroll
    for (int p = 0; p < NSTAGE - 1; ++p) {
        gemm_load_stage(base + p * STAGE_BYTES, Ah, Al, Bh, m0, n0, p * GBK, K, tid);
        cp_commit();
    }

    const uint32_t lrow  = (lane & 15);
    const uint32_t lkoff = (lane >> 4) << 4;

    for (int i = 0; i < nk; ++i) {
        cp_wait<NSTAGE - 2>();
        __syncthreads();

        const int nc = i + NSTAGE - 1;
        if (nc < nk)
            gemm_load_stage(base + (nc % NSTAGE) * STAGE_BYTES,
                            Ah, Al, Bh, m0, n0, nc * GBK, K, tid);
        cp_commit();

        const uint32_t sb = base + (i % NSTAGE) * STAGE_BYTES;
        #pragma unroll
        for (int ks = 0; ks < 4; ++ks) {
            uint32_t ah[2][4], al[2][4], bh[4][4];
            #pragma unroll
            for (int ma = 0; ma < 2; ++ma) {
                uint32_t off = (wm0 + ma * 16 + lrow) * 128 + ks * 32 + lkoff;
                uint32_t ad = sb + swz128(off);
                ldsm_x4(ah[ma], ad + AH_OFF);
                ldsm_x4(al[ma], ad + AL_OFF);
            }
            #pragma unroll
            for (int ng = 0; ng < 4; ++ng) {
                uint32_t off = (wn0 + ng * 16 + lrow) * 128 + ks * 32 + lkoff;
                ldsm_x4(bh[ng], sb + BH_OFF + swz128(off));
            }
            #pragma unroll
            for (int ma = 0; ma < 2; ++ma)
                #pragma unroll
                for (int ng = 0; ng < 4; ++ng)
                    #pragma unroll
                    for (int h = 0; h < 2; ++h) {
                        const int na = ng * 2 + h;
                        mma16816(acc[ma][na], ah[ma], bh[ng][h], bh[ng][2 + h]);
                        mma16816(acc[ma][na], al[ma], bh[ng][h], bh[ng][2 + h]);
                    }
        }
    }
}

__global__ __launch_bounds__(256, 1)
void gemm_fp16x2(const __half* __restrict__ Ah, const __half* __restrict__ Al,
                 const __half* __restrict__ Bh,
                 const float* __restrict__ R, float* __restrict__ C,
                 int N, int K)
{
    extern __shared__ char smem[];
    const int tid  = threadIdx.x;
    const int wid  = tid >> 5;
    const int lane = tid & 31;
    const int m0 = blockIdx.y * GBM;
    const int n0 = blockIdx.x * GBN;
    const uint32_t base = smem_u32(smem);

    float acc[2][8][4];
    gemm_mainloop(acc, Ah, Al, Bh, m0, n0, K, tid, wid, lane, base);

    const int wm0 = (wid & 3) * 32;
    const int wn0 = (wid >> 2) * 64;
    const int mrow = lane >> 2;
    const int ncol = (lane & 3) * 2;
    #pragma unroll
    for (int ma = 0; ma < 2; ++ma) {
        #pragma unroll
        for (int na = 0; na < 8; ++na) {
            const int m = m0 + wm0 + ma * 16 + mrow;
            const int n = n0 + wn0 + na * 8 + ncol;
            size_t o0 = (size_t)m * N + n;
            size_t o1 = o0 + (size_t)8 * N;
            float2 v0 = make_float2(acc[ma][na][0], acc[ma][na][1]);
            float2 v1 = make_float2(acc[ma][na][2], acc[ma][na][3]);
            if (R) {
                float2 r0 = *reinterpret_cast<const float2*>(R + o0);
                float2 r1 = *reinterpret_cast<const float2*>(R + o1);
                v0.x += r0.x; v0.y += r0.y;
                v1.x += r1.x; v1.y += r1.y;
            }
            *reinterpret_cast<float2*>(C + o0) = v0;
            *reinterpret_cast<float2*>(C + o1) = v1;
        }
    }
}

// W13 GEMM with fused SwiGLU epilogue. B = interleaved W1|W3 (phys N = 4096):
// phys rows [16t..16t+8) = W1 cols [8t..8t+8), [16t+8..16t+16) = W3 same cols.
// Writes gate (fp16 h/l) [M, DFFN].
__global__ __launch_bounds__(256, 1)
void gemm_fp16x2_swiglu(const __half* __restrict__ Ah, const __half* __restrict__ Al,
                        const __half* __restrict__ Bh,
                        __half* __restrict__ gh, __half* __restrict__ gl,
                        int K)
{
    extern __shared__ char smem[];
    const int tid  = threadIdx.x;
    const int wid  = tid >> 5;
    const int lane = tid & 31;
    const int m0 = blockIdx.y * GBM;
    const int n0 = blockIdx.x * GBN;
    const uint32_t base = smem_u32(smem);

    float acc[2][8][4];
    gemm_mainloop(acc, Ah, Al, Bh, m0, n0, K, tid, wid, lane, base);

    const int wm0 = (wid & 3) * 32;
    const int wn0 = (wid >> 2) * 64;
    const int mrow = lane >> 2;
    const int ncol = (lane & 3) * 2;
    const int gbase = ((n0 + wn0) >> 1);
    #pragma unroll
    for (int ma = 0; ma < 2; ++ma) {
        #pragma unroll
        for (int g = 0; g < 4; ++g) {
            const float* a1 = acc[ma][2 * g];       // W1 (silu input)
            const float* a3 = acc[ma][2 * g + 1];   // W3
            const int gcol = gbase + g * 8 + ncol;
            #pragma unroll
            for (int hf = 0; hf < 2; ++hf) {
                const int m = m0 + wm0 + ma * 16 + mrow + hf * 8;
                float x0 = a1[hf * 2 + 0], x1 = a1[hf * 2 + 1];
                float f0 = x0 / (1.0f + __expf(-x0)) * a3[hf * 2 + 0];
                float f1 = x1 / (1.0f + __expf(-x1)) * a3[hf * 2 + 1];
                __half h0 = __float2half_rn(f0);
                __half h1 = __float2half_rn(f1);
                __half l0 = __float2half_rn(f0 - __half2float(h0));
                __half l1 = __float2half_rn(f1 - __half2float(h1));
                size_t o = (size_t)m * DFFN + gcol;
                __half2 hv; hv.x = h0; hv.y = h1;
                __half2 lv; lv.x = l0; lv.y = l1;
                *reinterpret_cast<__half2*>(gh + o) = hv;
                *reinterpret_cast<__half2*>(gl + o) = lv;
            }
        }
    }
}

// ============ merged weight transpose: [K,N]f32 -> [N,K]fp16, one launch ======
#define NWJOBS 7
struct WJobs {
    const float* src[NWJOBS];
    __half* dst[NWJOBS];
    int K[NWJOBS];
    int N[NWJOBS];
    int mode[NWJOBS];
    int tile_off[NWJOBS + 1];
};

__global__ void wsplit_all_kernel(WJobs jobs)
{
    __shared__ float t[32][33];
    int tile = blockIdx.x;
    int j = 0;
    #pragma unroll
    for (int i = 0; i < NWJOBS; ++i)
        if (tile >= jobs.tile_off[i + 1]) j = i + 1;
    const int lt   = tile - jobs.tile_off[j];
    const int K    = jobs.K[j];
    const int N    = jobs.N[j];
    const int mode = jobs.mode[j];
    const float* W = jobs.src[j];
    __half* Th     = jobs.dst[j];
    const int ntx  = N >> 5;
    const int n0 = (lt % ntx) * 32;
    const int k0 = (lt / ntx) * 32;

    int tx = threadIdx.x & 31, ty = threadIdx.x >> 5;
    #pragma unroll
    for (int r = ty; r < 32; r += 8)
        t[r][tx] = W[(size_t)(k0 + r) * N + n0 + tx];
    __syncthreads();
    #pragma unroll
    for (int r = ty; r < 32; r += 8) {
        float v = t[tx][r];                       // W[k0+tx][n0+r]
        int n = n0 + r;
        int p = (mode == 0) ? n : (16 * (n >> 3) + (n & 7) + ((mode == 2) ? 8 : 0));
        Th[(size_t)p * K + k0 + tx] = __float2half_rn(v);
    }
}

// ---------------- RMSNorm + fp16 split ----------------------------------------
__global__ void rmsnorm_split_kernel(const float* __restrict__ x,
                                     const float* __restrict__ w,
                                     __half* __restrict__ oh,
                                     __half* __restrict__ ol) {
    const int D = DMODEL;
    size_t row = blockIdx.x;
    const float4* xr = reinterpret_cast<const float4*>(x + row * D);
    const float4* wr = reinterpret_cast<const float4*>(w);

    int tid = threadIdx.x;
    float4 xv = xr[tid];
    float ss = xv.x*xv.x + xv.y*xv.y + xv.z*xv.z + xv.w*xv.w;
    #pragma unroll
    for (int off = 16; off; off >>= 1)
        ss += __shfl_xor_sync(0xffffffffu, ss, off);
    __shared__ float red[8];
    int lane = tid & 31, warp = tid >> 5;
    if (lane == 0) red[warp] = ss;
    __syncthreads();
    if (tid < 32) {
        float v = (tid < 8) ? red[tid] : 0.0f;
        #pragma unroll
        for (int off = 4; off; off >>= 1)
            v += __shfl_xor_sync(0xffffffffu, v, off);
        if (tid == 0) red[0] = rsqrtf(v * (1.0f / D) + EPS);
    }
    __syncthreads();
    float inv = red[0];
    float4 wv = wr[tid];
    float f[4];
    f[0] = xv.x * inv * wv.x; f[1] = xv.y * inv * wv.y;
    f[2] = xv.z * inv * wv.z; f[3] = xv.w * inv * wv.w;

    alignas(8) __half hv[4], lv[4];
    #pragma unroll
    for (int j = 0; j < 4; ++j) {
        hv[j] = __float2half_rn(f[j]);
        lv[j] = __float2half_rn(f[j] - __half2float(hv[j]));
    }
    size_t b = row * D + tid * 4;
    *reinterpret_cast<uint2*>(oh + b) = *reinterpret_cast<uint2*>(hv);
    *reinterpret_cast<uint2*>(ol + b) = *reinterpret_cast<uint2*>(lv);
}

// ---------------- Tiled windowed causal attention (32 q / block) --------------
// 32 queries per block -> 256 blocks; span <= 95; smem ~62.6KB -> 2-3 CTA/SM.
#define ATQ  32
#define SPAD 97
#define KPAD 68
#define VPAD 132
#define S_FLOATS (ATQ * SPAD)                      // 3104
#define SCR_FLOATS (95 * VPAD)                     // 12540 >= 32*68+95*68 = 8636
#define ATTN_SMEM ((S_FLOATS + SCR_FLOATS) * 4)    // 62576 B

__global__ __launch_bounds__(256)
void attn_tile_kernel(const float* __restrict__ qkv,
                      __half* __restrict__ oh,
                      __half* __restrict__ ol)
{
    extern __shared__ float sm[];
    float* S   = sm;                 // [32][SPAD]
    float* scr = sm + S_FLOATS;
    float* Qc  = scr;                // [32][KPAD]   (phase 1)
    float* Kc  = scr + ATQ * KPAD;   // [95][KPAD]   (phase 1)
    float* Vc  = scr;                // [95][VPAD]   (phase 3)

    const int tid  = threadIdx.x;
    const int ty   = tid >> 5;
    const int lane = tid & 31;
    const int blk  = blockIdx.x;
    const int b    = blk >> 6;               // 64 tiles per batch
    const int t0   = (blk & 63) * ATQ;
    const int jlo  = (t0 == 0) ? 0 : t0 - (WIN - 1);
    const int span = t0 + ATQ - jlo;         // <= 95
    const size_t rowbase = (size_t)b * SEQ;
    const float scale = 0.03125f;

    const int qi0 = ty * 4;                  // 4 queries per warp
    const int bs  = (t0 == 0) ? 0 : qi0;     // band start of this warp's queries

    // zero S
    for (int i = tid; i < S_FLOATS; i += 256) S[i] = 0.0f;

    // clamped key slots for this lane (3 slots cover band width <= 67)
    int kkc[3];
    #pragma unroll
    for (int r = 0; r < 3; ++r) {
        int kk = bs + lane + 32 * r;
        kkc[r] = kk < span ? kk : span - 1;
    }

    float acc[4][3];
    #pragma unroll
    for (int q = 0; q < 4; ++q)
        #pragma unroll
        for (int r = 0; r < 3; ++r) acc[q][r] = 0.0f;

    // ---- phase 1: scores over 16 d-chunks of 64 ----
    for (int dc = 0; dc < 16; ++dc) {
        const int d0 = dc * 64;
        {   // load Qc [32][64]: thread -> (row = tid>>3, 8 floats)
            int r = tid >> 3, c0 = (tid & 7) * 8;
            const float* src = qkv + (rowbase + t0 + r) * 3072 + d0 + c0;
            float* dst = Qc + r * KPAD + c0;
            *reinterpret_cast<float4*>(dst)     = *reinterpret_cast<const float4*>(src);
            *reinterpret_cast<float4*>(dst + 4) = *reinterpret_cast<const float4*>(src + 4);
        }
        {   // load Kc [span][64]
            int r = tid >> 1, c0 = (tid & 1) * 32;
            if (r < span) {
                const float* src = qkv + (rowbase + jlo + r) * 3072 + 1024 + d0 + c0;
                float* dst = Kc + r * KPAD + c0;
                #pragma unroll
                for (int s = 0; s < 8; ++s)
                    *reinterpret_cast<float4*>(dst + s * 4) =
                        *reinterpret_cast<const float4*>(src + s * 4);
            }
        }
        __syncthreads();

        #pragma unroll 4
        for (int d4 = 0; d4 < 64; d4 += 4) {
            float4 kf[3];
            #pragma unroll
            for (int r = 0; r < 3; ++r)
                kf[r] = *reinterpret_cast<const float4*>(Kc + kkc[r] * KPAD + d4);
            #pragma unroll
            for (int q = 0; q < 4; ++q) {
                float4 qf = *reinterpret_cast<const float4*>(Qc + (qi0 + q) * KPAD + d4);
                #pragma unroll
                for (int r = 0; r < 3; ++r) {
                    acc[q][r] = fmaf(qf.x, kf[r].x, acc[q][r]);
                    acc[q][r] = fmaf(qf.y, kf[r].y, acc[q][r]);
                    acc[q][r] = fmaf(qf.z, kf[r].z, acc[q][r]);
                    acc[q][r] = fmaf(qf.w, kf[r].w, acc[q][r]);
                }
            }
        }
        __syncthreads();
    }

    // write band scores to S (out-of-window entries fixed by softmax phase)
    #pragma unroll
    for (int q = 0; q < 4; ++q)
        #pragma unroll
        for (int r = 0; r < 3; ++r) {
            int kk = bs + lane + 32 * r;
            if (kk < span) S[(qi0 + q) * SPAD + kk] = acc[q][r] * scale;
        }
    __syncthreads();

    // ---- phase 2: softmax (one thread per query) ----
    if (tid < ATQ) {
        const int qi  = tid;
        const int ti  = t0 + qi;
        const int wlo = ((ti >= WIN - 1) ? ti - (WIN - 1) : 0) - jlo;
        const int whi = ti - jlo;
        float* row = S + qi * SPAD;
        float m = -1e30f;
        for (int jj = wlo; jj <= whi; ++jj) m = fmaxf(m, row[jj]);
        float sum = 0.0f;
        for (int jj = wlo; jj <= whi; ++jj) {
            float e = __expf(row[jj] - m);
            row[jj] = e;
            sum += e;
        }
        float inv = 1.0f / sum;
        for (int jj = 0; jj < SPAD; ++jj)
            row[jj] = (jj >= wlo && jj <= whi) ? row[jj] * inv : 0.0f;
    }
    __syncthreads();

    // ---- phase 3: PV over 8 d-chunks of 128 ----
    const int js = bs;
    const int jeRaw = (t0 == 0) ? (qi0 + 3) : (qi0 + 3 + WIN - 1);
    const int je = jeRaw < span - 1 ? jeRaw : span - 1;
    for (int vc = 0; vc < 8; ++vc) {
        const int d0 = vc * 128;
        {   // load Vc [span][128]
            int r = tid >> 1, c0 = (tid & 1) * 64;
            if (r < span) {
                const float* src = qkv + (rowbase + jlo + r) * 3072 + 2048 + d0 + c0;
                float* dst = Vc + r * VPAD + c0;
                #pragma unroll
                for (int s = 0; s < 16; ++s)
                    *reinterpret_cast<float4*>(dst + s * 4) =
                        *reinterpret_cast<const float4*>(src + s * 4);
            }
        }
        __syncthreads();

        float4 out[4];
        #pragma unroll
        for (int q = 0; q < 4; ++q) out[q] = make_float4(0.f, 0.f, 0.f, 0.f);

        for (int jj = js; jj <= je; ++jj) {
            float4 v = *reinterpret_cast<const float4*>(Vc + jj * VPAD + lane * 4);
            #pragma unroll
            for (int q = 0; q < 4; ++q) {
                float w = S[(qi0 + q) * SPAD + jj];
                out[q].x = fmaf(w, v.x, out[q].x);
                out[q].y = fmaf(w, v.y, out[q].y);
                out[q].z = fmaf(w, v.z, out[q].z);
                out[q].w = fmaf(w, v.w, out[q].w);
            }
        }

        #pragma unroll
        for (int q = 0; q < 4; ++q) {
            size_t o = (rowbase + t0 + qi0 + q) * DMODEL + d0 + lane * 4;
            float f[4] = {out[q].x, out[q].y, out[q].z, out[q].w};
            alignas(8) __half hv[4], lv[4];
            #pragma unroll
            for (int j = 0; j < 4; ++j) {
                hv[j] = __float2half_rn(f[j]);
                lv[j] = __float2half_rn(f[j] - __half2float(hv[j]));
            }
            *reinterpret_cast<uint2*>(oh + o) = *reinterpret_cast<uint2*>(hv);
            *reinterpret_cast<uint2*>(ol + o) = *reinterpret_cast<uint2*>(lv);
        }
        __syncthreads();
    }
}

// ---------------- launch -------------------------------------------------------
extern "C" void kernel_launch(void* const* d_in, const int* in_sizes, int n_in,
                              void* d_out, int out_size) {
    const float* x       = (const float*)d_in[0];
    const float* norm1_w = (const float*)d_in[1];
    const float* norm2_w = (const float*)d_in[2];
    const float* Wq      = (const float*)d_in[3];
    const float* Wk      = (const float*)d_in[4];
    const float* Wv      = (const float*)d_in[5];
    const float* Wo      = (const float*)d_in[6];
    const float* W1      = (const float*)d_in[7];
    const float* W2      = (const float*)d_in[8];
    const float* W3      = (const float*)d_in[9];
    float* out = (float*)d_out;

    float *p_qkv, *p_xmid;
    cudaGetSymbolAddress((void**)&p_qkv,  g_qkv);
    cudaGetSymbolAddress((void**)&p_xmid, g_xmid);

    __half *xn_h, *xn_l, *att_h, *att_l, *xn2_h, *xn2_l, *gate_h, *gate_l;
    cudaGetSymbolAddress((void**)&xn_h,  g_xn_h);
    cudaGetSymbolAddress((void**)&xn_l,  g_xn_l);
    cudaGetSymbolAddress((void**)&att_h, g_att_h);
    cudaGetSymbolAddress((void**)&att_l, g_att_l);
    cudaGetSymbolAddress((void**)&xn2_h, g_xn2_h);
    cudaGetSymbolAddress((void**)&xn2_l, g_xn2_l);
    cudaGetSymbolAddress((void**)&gate_h, g_gate_h);
    cudaGetSymbolAddress((void**)&gate_l, g_gate_l);

    __half *wqkv, *wo, *w13i, *w2;
    cudaGetSymbolAddress((void**)&wqkv, g_wqkv);
    cudaGetSymbolAddress((void**)&wo,   g_wo);
    cudaGetSymbolAddress((void**)&w13i, g_w13i);
    cudaGetSymbolAddress((void**)&w2,   g_w2);

    cudaFuncSetAttribute(gemm_fp16x2, cudaFuncAttributeMaxDynamicSharedMemorySize, GEMM_SMEM);
    cudaFuncSetAttribute(gemm_fp16x2_swiglu, cudaFuncAttributeMaxDynamicSharedMemorySize, GEMM_SMEM);
    cudaFuncSetAttribute(attn_tile_kernel, cudaFuncAttributeMaxDynamicSharedMemorySize, ATTN_SMEM);

    const int M = MROWS;                 // 8192
    const int DD = DMODEL * DMODEL;
    dim3 gQKV(3 * DMODEL / GBN, M / GBM);   // (24, 64)
    dim3 gD  (DMODEL / GBN,     M / GBM);   // (8, 64)
    dim3 gF13(2 * DFFN / GBN,   M / GBM);   // (32, 64)

    // merged weight transpose (7 jobs, one launch)
    {
        WJobs jb;
        const float* srcs[NWJOBS] = {Wq, Wk, Wv, Wo, W1, W3, W2};
        __half* dsts[NWJOBS] = {wqkv, wqkv + DD, wqkv + 2*DD, wo, w13i, w13i, w2};
        int Ks[NWJOBS]    = {DMODEL, DMODEL, DMODEL, DMODEL, DMODEL, DMODEL, DFFN};
        int Ns[NWJOBS]    = {DMODEL, DMODEL, DMODEL, DMODEL, DFFN,   DFFN,   DMODEL};
        int modes[NWJOBS] = {0, 0, 0, 0, 1, 2, 0};
        int off = 0;
        for (int i = 0; i < NWJOBS; ++i) {
            jb.src[i] = srcs[i]; jb.dst[i] = dsts[i];
            jb.K[i] = Ks[i]; jb.N[i] = Ns[i]; jb.mode[i] = modes[i];
            jb.tile_off[i] = off;
            off += (Ns[i] >> 5) * (Ks[i] >> 5);
        }
        jb.tile_off[NWJOBS] = off;
        wsplit_all_kernel<<<off, 256>>>(jb);
    }

    // 1. norm1 (+ split)
    rmsnorm_split_kernel<<<M, 256>>>(x, norm1_w, xn_h, xn_l);
    // 2. fused QKV projection -> [M, 3072]
    gemm_fp16x2<<<gQKV, 256, GEMM_SMEM>>>(xn_h, xn_l, wqkv, nullptr, p_qkv, 3*DMODEL, DMODEL);
    // 3. tiled windowed attention (+ split)
    attn_tile_kernel<<<M / ATQ, 256, ATTN_SMEM>>>(p_qkv, att_h, att_l);
    // 4. x_mid = x + attended @ Wo
    gemm_fp16x2<<<gD, 256, GEMM_SMEM>>>(att_h, att_l, wo, x, p_xmid, DMODEL, DMODEL);
    // 5. norm2 (+ split)
    rmsnorm_split_kernel<<<M, 256>>>(p_xmid, norm2_w, xn2_h, xn2_l);
    // 6. fused FFN up projection + SwiGLU -> gate fp16 h/l [M, 2048]
    gemm_fp16x2_swiglu<<<gF13, 256, GEMM_SMEM>>>(xn2_h, xn2_l, w13i, gate_h, gate_l, DMODEL);
    // 7. out = x_mid + gate @ W2
    gemm_fp16x2<<<gD, 256, GEMM_SMEM>>>(gate_h, gate_l, w2, p_xmid, out, DMODEL, DFFN);
}